// round 1
// baseline (speedup 1.0000x reference)
#include <cuda_runtime.h>
#include <cuda_bf16.h>
#include <cstdint>

// ---------------- problem-size constants (from reference) ----------------
#define MAX_N 50176
#define MAX_E 800000
#define D 128            // feature dim (both in and out)

// ---------------- device scratch (no allocations allowed) ----------------
__device__ float g_h[(size_t)MAX_N * D];     // post LN+ReLU+mask features
__device__ float g_agg[(size_t)MAX_N * D];   // mean-aggregated neighbor feats
__device__ float g_wt[2 * D * D];            // fused transposed weights [256][128]
__device__ int   g_deg[MAX_N];
__device__ int   g_start[MAX_N];
__device__ int   g_cursor[MAX_N];
__device__ int   g_csr[MAX_E];
__device__ int   g_bsums[1024];
__device__ int   g_is32;                     // 1 if edge_index is int32

// ---------------- edge dtype detection ----------------
__global__ void detect_dtype_kernel(const unsigned long long* __restrict__ e,
                                    int nwords, unsigned long long N) {
    int bad = 0;
    for (int i = threadIdx.x; i < nwords; i += blockDim.x) {
        if (e[i] >= N) bad = 1;   // genuine int64 indices are all < N
    }
    bad = __syncthreads_or(bad);
    if (threadIdx.x == 0) g_is32 = bad;
}

__device__ __forceinline__ int edge_at(const void* p, long long idx, int is32) {
    if (is32) return ((const int*)p)[idx];
    return (int)((const long long*)p)[idx];
}

// ---------------- Stage A: LayerNorm + ReLU + dropout mask ----------------
__global__ void ln_relu_mask_kernel(const float* __restrict__ x,
                                    const float* __restrict__ mask,
                                    const float* __restrict__ gamma,
                                    const float* __restrict__ beta,
                                    int N) {
    int warp = (blockIdx.x * blockDim.x + threadIdx.x) >> 5;
    int lane = threadIdx.x & 31;
    if (warp >= N) return;
    const float4* xr = (const float4*)(x + (size_t)warp * D);
    float4 v = xr[lane];
    float s  = v.x + v.y + v.z + v.w;
    float ss = v.x * v.x + v.y * v.y + v.z * v.z + v.w * v.w;
    #pragma unroll
    for (int o = 16; o; o >>= 1) {
        s  += __shfl_xor_sync(0xffffffffu, s,  o);
        ss += __shfl_xor_sync(0xffffffffu, ss, o);
    }
    float mu  = s * (1.0f / D);
    float var = ss * (1.0f / D) - mu * mu;
    float inv = rsqrtf(var + 1e-5f);
    float4 g = ((const float4*)gamma)[lane];
    float4 b = ((const float4*)beta)[lane];
    float4 m = ((const float4*)(mask + (size_t)warp * D))[lane];
    float4 o;
    o.x = fmaxf((v.x - mu) * inv * g.x + b.x, 0.0f) * m.x;
    o.y = fmaxf((v.y - mu) * inv * g.y + b.y, 0.0f) * m.y;
    o.z = fmaxf((v.z - mu) * inv * g.z + b.z, 0.0f) * m.z;
    o.w = fmaxf((v.w - mu) * inv * g.w + b.w, 0.0f) * m.w;
    ((float4*)(g_h + (size_t)warp * D))[lane] = o;
}

// ---------------- Stage B1: degree count ----------------
__global__ void zero_deg_kernel(int N) {
    int i = blockIdx.x * blockDim.x + threadIdx.x;
    if (i < N) g_deg[i] = 0;
}

__global__ void count_deg_kernel(const void* __restrict__ edges, int E) {
    int is32 = g_is32;
    for (long long e = blockIdx.x * (long long)blockDim.x + threadIdx.x;
         e < E; e += (long long)gridDim.x * blockDim.x) {
        int dst = edge_at(edges, (long long)E + e, is32);
        atomicAdd(&g_deg[dst], 1);
    }
}

// ---------------- Stage B2: exclusive scan (3 kernels) ----------------
__global__ void scan1_kernel(int N) {
    __shared__ int sh[1024];
    int i = blockIdx.x * 1024 + threadIdx.x;
    int v = (i < N) ? g_deg[i] : 0;
    sh[threadIdx.x] = v;
    __syncthreads();
    #pragma unroll
    for (int off = 1; off < 1024; off <<= 1) {
        int t = (threadIdx.x >= off) ? sh[threadIdx.x - off] : 0;
        __syncthreads();
        sh[threadIdx.x] += t;
        __syncthreads();
    }
    if (i < N) g_start[i] = sh[threadIdx.x] - v;   // exclusive
    if (threadIdx.x == 1023) g_bsums[blockIdx.x] = sh[1023];
}

__global__ void scan2_kernel(int nb) {
    __shared__ int sh[1024];
    int v = (threadIdx.x < nb) ? g_bsums[threadIdx.x] : 0;
    sh[threadIdx.x] = v;
    __syncthreads();
    #pragma unroll
    for (int off = 1; off < 1024; off <<= 1) {
        int t = (threadIdx.x >= off) ? sh[threadIdx.x - off] : 0;
        __syncthreads();
        sh[threadIdx.x] += t;
        __syncthreads();
    }
    if (threadIdx.x < nb) g_bsums[threadIdx.x] = sh[threadIdx.x] - v;  // exclusive
}

__global__ void add_offsets_kernel(int N) {
    int i = blockIdx.x * blockDim.x + threadIdx.x;
    if (i < N) {
        int s = g_start[i] + g_bsums[i >> 10];
        g_start[i] = s;
        g_cursor[i] = s;
    }
}

// ---------------- Stage B3: scatter edges into CSR ----------------
__global__ void scatter_kernel(const void* __restrict__ edges, int E) {
    int is32 = g_is32;
    for (long long e = blockIdx.x * (long long)blockDim.x + threadIdx.x;
         e < E; e += (long long)gridDim.x * blockDim.x) {
        int src = edge_at(edges, e, is32);
        int dst = edge_at(edges, (long long)E + e, is32);
        int pos = atomicAdd(&g_cursor[dst], 1);
        g_csr[pos] = src;
    }
}

// ---------------- Stage B4: mean aggregation (warp per node) ----------------
__global__ void aggregate_kernel(int N) {
    int warp = (blockIdx.x * blockDim.x + threadIdx.x) >> 5;
    int lane = threadIdx.x & 31;
    if (warp >= N) return;
    int st = g_start[warp];
    int d  = g_deg[warp];
    const float4* hv = (const float4*)g_h;
    float4 acc = make_float4(0.f, 0.f, 0.f, 0.f);
    int j = st, end = st + d;
    // 4-way unroll for MLP
    for (; j + 4 <= end; j += 4) {
        int s0 = g_csr[j], s1 = g_csr[j + 1], s2 = g_csr[j + 2], s3 = g_csr[j + 3];
        float4 a0 = hv[(size_t)s0 * 32 + lane];
        float4 a1 = hv[(size_t)s1 * 32 + lane];
        float4 a2 = hv[(size_t)s2 * 32 + lane];
        float4 a3 = hv[(size_t)s3 * 32 + lane];
        acc.x += a0.x + a1.x + a2.x + a3.x;
        acc.y += a0.y + a1.y + a2.y + a3.y;
        acc.z += a0.z + a1.z + a2.z + a3.z;
        acc.w += a0.w + a1.w + a2.w + a3.w;
    }
    for (; j < end; ++j) {
        int s0 = g_csr[j];
        float4 a0 = hv[(size_t)s0 * 32 + lane];
        acc.x += a0.x; acc.y += a0.y; acc.z += a0.z; acc.w += a0.w;
    }
    float invd = 1.0f / fmaxf((float)d, 1.0f);
    acc.x *= invd; acc.y *= invd; acc.z *= invd; acc.w *= invd;
    ((float4*)g_agg)[(size_t)warp * 32 + lane] = acc;
}

// ---------------- Stage C0: build fused transposed weights ----------------
__global__ void build_wt_kernel(const float* __restrict__ wl,
                                const float* __restrict__ wr) {
    int idx = blockIdx.x * blockDim.x + threadIdx.x;   // [0, 256*128)
    if (idx < 2 * D * D) {
        int k = idx >> 7;
        int j = idx & 127;
        g_wt[idx] = (k < D) ? wl[j * D + k] : wr[j * D + (k - D)];
    }
}

// ---------------- Stage C: fused GEMM out = agg@wl^T + h@wr^T + b ----------
// BM=128, BN=128, BK=16; 256 threads, 8x8 outputs per thread.
__global__ __launch_bounds__(256) void gemm_kernel(const float* __restrict__ bias,
                                                   float* __restrict__ out, int N) {
    __shared__ float As[16][132];
    __shared__ float Bs[16][128];
    int tid = threadIdx.x;
    int tx = tid & 15;           // output col group
    int ty = tid >> 4;           // output row group
    int rowBase = blockIdx.x * 128;
    float acc[8][8];
    #pragma unroll
    for (int i = 0; i < 8; i++)
        #pragma unroll
        for (int j = 0; j < 8; j++) acc[i][j] = 0.0f;

    for (int k0 = 0; k0 < 256; k0 += 16) {
        const float* A = (k0 < 128) ? (g_agg + k0) : (g_h + (k0 - 128));
        // load A tile (128x16), transposed into shared
        #pragma unroll
        for (int it = 0; it < 2; ++it) {
            int m = (tid >> 2) + it * 64;
            int c = (tid & 3) * 4;
            int row = rowBase + m;
            float4 v = make_float4(0.f, 0.f, 0.f, 0.f);
            if (row < N) v = *(const float4*)(A + (size_t)row * D + c);
            As[c + 0][m] = v.x;
            As[c + 1][m] = v.y;
            As[c + 2][m] = v.z;
            As[c + 3][m] = v.w;
        }
        // load B tile (16x128) contiguous
        #pragma unroll
        for (int it = 0; it < 2; ++it) {
            int idx = tid + it * 256;
            ((float4*)Bs)[idx] = ((const float4*)(g_wt + k0 * D))[idx];
        }
        __syncthreads();
        #pragma unroll
        for (int kk = 0; kk < 16; ++kk) {
            float a[8], b[8];
            *(float4*)(a + 0) = *(float4*)&As[kk][ty * 8 + 0];
            *(float4*)(a + 4) = *(float4*)&As[kk][ty * 8 + 4];
            *(float4*)(b + 0) = *(float4*)&Bs[kk][tx * 8 + 0];
            *(float4*)(b + 4) = *(float4*)&Bs[kk][tx * 8 + 4];
            #pragma unroll
            for (int i = 0; i < 8; i++)
                #pragma unroll
                for (int j = 0; j < 8; j++)
                    acc[i][j] = fmaf(a[i], b[j], acc[i][j]);
        }
        __syncthreads();
    }
    // epilogue: add bias, store
    float bb[8];
    *(float4*)(bb + 0) = *(const float4*)(bias + tx * 8 + 0);
    *(float4*)(bb + 4) = *(const float4*)(bias + tx * 8 + 4);
    #pragma unroll
    for (int i = 0; i < 8; i++) {
        int row = rowBase + ty * 8 + i;
        if (row < N) {
            float4 o0 = make_float4(acc[i][0] + bb[0], acc[i][1] + bb[1],
                                    acc[i][2] + bb[2], acc[i][3] + bb[3]);
            float4 o1 = make_float4(acc[i][4] + bb[4], acc[i][5] + bb[5],
                                    acc[i][6] + bb[6], acc[i][7] + bb[7]);
            *(float4*)(out + (size_t)row * D + tx * 8 + 0) = o0;
            *(float4*)(out + (size_t)row * D + tx * 8 + 4) = o1;
        }
    }
}

// ---------------- launch ----------------
extern "C" void kernel_launch(void* const* d_in, const int* in_sizes, int n_in,
                              void* d_out, int out_size) {
    const float* x     = (const float*)d_in[0];
    const void*  edges =               d_in[1];
    const float* mask  = (const float*)d_in[2];
    const float* gamma = (const float*)d_in[3];
    const float* beta  = (const float*)d_in[4];
    const float* wl    = (const float*)d_in[5];
    const float* bl    = (const float*)d_in[6];
    const float* wr    = (const float*)d_in[7];
    float* out = (float*)d_out;

    int N = in_sizes[0] / D;
    int E = in_sizes[1] / 2;

    // dtype detect: scan first words as u64 (safe for both layouts: int32 buffer
    // has E u64 words, int64 buffer has 2E)
    int nwords = E < 2048 ? E : 2048;
    detect_dtype_kernel<<<1, 1024>>>((const unsigned long long*)edges, nwords,
                                     (unsigned long long)N);

    // Stage A
    ln_relu_mask_kernel<<<(N + 7) / 8, 256>>>(x, mask, gamma, beta, N);

    // Stage B: CSR build
    zero_deg_kernel<<<(N + 255) / 256, 256>>>(N);
    count_deg_kernel<<<1024, 256>>>(edges, E);
    int nb = (N + 1023) / 1024;
    scan1_kernel<<<nb, 1024>>>(N);
    scan2_kernel<<<1, 1024>>>(nb);
    add_offsets_kernel<<<(N + 255) / 256, 256>>>(N);
    scatter_kernel<<<1024, 256>>>(edges, E);

    // Stage B: aggregate
    aggregate_kernel<<<(N + 7) / 8, 256>>>(N);

    // Stage C
    build_wt_kernel<<<(2 * D * D + 255) / 256, 256>>>(wl, wr);
    gemm_kernel<<<(N + 127) / 128, 256>>>(bl, out, N);
}

// round 3
// speedup vs baseline: 1.0396x; 1.0396x over previous
#include <cuda_runtime.h>
#include <cuda_bf16.h>
#include <cstdint>

// ---------------- problem-size constants ----------------
#define MAX_N 50176
#define MAX_E 800000
#define D 128

// ---------------- device scratch ----------------
__device__ float g_h[(size_t)MAX_N * D];                 // fp32 LN output (for aggregation)
__device__ __nv_bfloat16 g_Ahi[(size_t)MAX_N * 256];     // [agg_hi | h_hi]
__device__ __nv_bfloat16 g_Alo[(size_t)MAX_N * 256];     // [agg_lo | h_lo]
__device__ __nv_bfloat16 g_Bhi[128 * 256];               // fused weights hi [n][k]
__device__ __nv_bfloat16 g_Blo[128 * 256];               // fused weights lo
__device__ int   g_deg[MAX_N];
__device__ int   g_start[MAX_N];
__device__ int   g_cursor[MAX_N];
__device__ int   g_csr[MAX_E];
__device__ int   g_bsums[1024];
__device__ int   g_is32;

// ---------------- helpers ----------------
__device__ __forceinline__ uint32_t smem_u32(const void* p) {
    uint32_t a;
    asm("{ .reg .u64 t; cvta.to.shared.u64 t, %1; cvt.u32.u64 %0, t; }" : "=r"(a) : "l"(p));
    return a;
}

__device__ __forceinline__ void split_bf16(float v, __nv_bfloat16& hi, __nv_bfloat16& lo) {
    hi = __float2bfloat16(v);
    lo = __float2bfloat16(v - __bfloat162float(hi));
}

__device__ __forceinline__ void ldmat_x4(uint32_t addr, uint32_t* r) {
    asm volatile("ldmatrix.sync.aligned.m8n8.x4.shared.b16 {%0,%1,%2,%3}, [%4];"
                 : "=r"(r[0]), "=r"(r[1]), "=r"(r[2]), "=r"(r[3]) : "r"(addr));
}

__device__ __forceinline__ void mma16816(float* d, const uint32_t* a,
                                         uint32_t b0, uint32_t b1) {
    asm volatile(
        "mma.sync.aligned.m16n8k16.row.col.f32.bf16.bf16.f32 "
        "{%0,%1,%2,%3}, {%4,%5,%6,%7}, {%8,%9}, {%0,%1,%2,%3};"
        : "+f"(d[0]), "+f"(d[1]), "+f"(d[2]), "+f"(d[3])
        : "r"(a[0]), "r"(a[1]), "r"(a[2]), "r"(a[3]), "r"(b0), "r"(b1));
}

// ---------------- edge dtype detection ----------------
__global__ void detect_dtype_kernel(const unsigned long long* __restrict__ e,
                                    int nwords, unsigned long long N) {
    int bad = 0;
    for (int i = threadIdx.x; i < nwords; i += blockDim.x)
        if (e[i] >= N) bad = 1;
    bad = __syncthreads_or(bad);
    if (threadIdx.x == 0) g_is32 = bad;
}

__device__ __forceinline__ int edge_at(const void* p, long long idx, int is32) {
    if (is32) return ((const int*)p)[idx];
    return (int)((const long long*)p)[idx];
}

// ---------------- Stage A: LayerNorm + ReLU + dropout mask ----------------
__global__ void ln_relu_mask_kernel(const float* __restrict__ x,
                                    const float* __restrict__ mask,
                                    const float* __restrict__ gamma,
                                    const float* __restrict__ beta,
                                    int N) {
    int warp = (blockIdx.x * blockDim.x + threadIdx.x) >> 5;
    int lane = threadIdx.x & 31;
    if (warp >= N) return;
    const float4* xr = (const float4*)(x + (size_t)warp * D);
    float4 v = xr[lane];
    float s  = v.x + v.y + v.z + v.w;
    float ss = v.x * v.x + v.y * v.y + v.z * v.z + v.w * v.w;
    #pragma unroll
    for (int o = 16; o; o >>= 1) {
        s  += __shfl_xor_sync(0xffffffffu, s,  o);
        ss += __shfl_xor_sync(0xffffffffu, ss, o);
    }
    float mu  = s * (1.0f / D);
    float var = ss * (1.0f / D) - mu * mu;
    float inv = rsqrtf(var + 1e-5f);
    float4 g = ((const float4*)gamma)[lane];
    float4 b = ((const float4*)beta)[lane];
    float4 m = ((const float4*)(mask + (size_t)warp * D))[lane];
    float4 o;
    o.x = fmaxf((v.x - mu) * inv * g.x + b.x, 0.0f) * m.x;
    o.y = fmaxf((v.y - mu) * inv * g.y + b.y, 0.0f) * m.y;
    o.z = fmaxf((v.z - mu) * inv * g.z + b.z, 0.0f) * m.z;
    o.w = fmaxf((v.w - mu) * inv * g.w + b.w, 0.0f) * m.w;
    ((float4*)(g_h + (size_t)warp * D))[lane] = o;
    __nv_bfloat16 hx, hy, hz, hw, lx, ly, lz, lw;
    split_bf16(o.x, hx, lx); split_bf16(o.y, hy, ly);
    split_bf16(o.z, hz, lz); split_bf16(o.w, hw, lw);
    size_t base = (size_t)warp * 256 + 128 + lane * 4;
    *(__nv_bfloat162*)(g_Ahi + base)     = __halves2bfloat162(hx, hy);
    *(__nv_bfloat162*)(g_Ahi + base + 2) = __halves2bfloat162(hz, hw);
    *(__nv_bfloat162*)(g_Alo + base)     = __halves2bfloat162(lx, ly);
    *(__nv_bfloat162*)(g_Alo + base + 2) = __halves2bfloat162(lz, lw);
}

// ---------------- Stage B: CSR build ----------------
__global__ void zero_deg_kernel(int N) {
    int i = blockIdx.x * blockDim.x + threadIdx.x;
    if (i < N) g_deg[i] = 0;
}

__global__ void count_deg_kernel(const void* __restrict__ edges, int E) {
    int is32 = g_is32;
    for (long long e = blockIdx.x * (long long)blockDim.x + threadIdx.x;
         e < E; e += (long long)gridDim.x * blockDim.x) {
        int dst = edge_at(edges, (long long)E + e, is32);
        atomicAdd(&g_deg[dst], 1);
    }
}

__global__ void scan1_kernel(int N) {
    __shared__ int sh[1024];
    int i = blockIdx.x * 1024 + threadIdx.x;
    int v = (i < N) ? g_deg[i] : 0;
    sh[threadIdx.x] = v;
    __syncthreads();
    #pragma unroll
    for (int off = 1; off < 1024; off <<= 1) {
        int t = (threadIdx.x >= off) ? sh[threadIdx.x - off] : 0;
        __syncthreads();
        sh[threadIdx.x] += t;
        __syncthreads();
    }
    if (i < N) g_start[i] = sh[threadIdx.x] - v;
    if (threadIdx.x == 1023) g_bsums[blockIdx.x] = sh[1023];
}

__global__ void scan2_kernel(int nb) {
    __shared__ int sh[1024];
    int v = (threadIdx.x < nb) ? g_bsums[threadIdx.x] : 0;
    sh[threadIdx.x] = v;
    __syncthreads();
    #pragma unroll
    for (int off = 1; off < 1024; off <<= 1) {
        int t = (threadIdx.x >= off) ? sh[threadIdx.x - off] : 0;
        __syncthreads();
        sh[threadIdx.x] += t;
        __syncthreads();
    }
    if (threadIdx.x < nb) g_bsums[threadIdx.x] = sh[threadIdx.x] - v;
}

__global__ void add_offsets_kernel(int N) {
    int i = blockIdx.x * blockDim.x + threadIdx.x;
    if (i < N) {
        int s = g_start[i] + g_bsums[i >> 10];
        g_start[i] = s;
        g_cursor[i] = s;
    }
}

__global__ void scatter_kernel(const void* __restrict__ edges, int E) {
    int is32 = g_is32;
    for (long long e = blockIdx.x * (long long)blockDim.x + threadIdx.x;
         e < E; e += (long long)gridDim.x * blockDim.x) {
        int src = edge_at(edges, e, is32);
        int dst = edge_at(edges, (long long)E + e, is32);
        int pos = atomicAdd(&g_cursor[dst], 1);
        g_csr[pos] = src;
    }
}

// ---------------- Stage B4: mean aggregation + split-bf16 ----------------
__global__ void aggregate_kernel(int N) {
    int warp = (blockIdx.x * blockDim.x + threadIdx.x) >> 5;
    int lane = threadIdx.x & 31;
    if (warp >= N) return;
    int st = g_start[warp];
    int d  = g_deg[warp];
    const float4* hv = (const float4*)g_h;
    float4 acc = make_float4(0.f, 0.f, 0.f, 0.f);
    int j = st, end = st + d;
    for (; j + 4 <= end; j += 4) {
        int s0 = g_csr[j], s1 = g_csr[j + 1], s2 = g_csr[j + 2], s3 = g_csr[j + 3];
        float4 a0 = hv[(size_t)s0 * 32 + lane];
        float4 a1 = hv[(size_t)s1 * 32 + lane];
        float4 a2 = hv[(size_t)s2 * 32 + lane];
        float4 a3 = hv[(size_t)s3 * 32 + lane];
        acc.x += a0.x + a1.x + a2.x + a3.x;
        acc.y += a0.y + a1.y + a2.y + a3.y;
        acc.z += a0.z + a1.z + a2.z + a3.z;
        acc.w += a0.w + a1.w + a2.w + a3.w;
    }
    for (; j < end; ++j) {
        int s0 = g_csr[j];
        float4 a0 = hv[(size_t)s0 * 32 + lane];
        acc.x += a0.x; acc.y += a0.y; acc.z += a0.z; acc.w += a0.w;
    }
    float invd = 1.0f / fmaxf((float)d, 1.0f);
    acc.x *= invd; acc.y *= invd; acc.z *= invd; acc.w *= invd;
    __nv_bfloat16 hx, hy, hz, hw, lx, ly, lz, lw;
    split_bf16(acc.x, hx, lx); split_bf16(acc.y, hy, ly);
    split_bf16(acc.z, hz, lz); split_bf16(acc.w, hw, lw);
    size_t base = (size_t)warp * 256 + lane * 4;
    *(__nv_bfloat162*)(g_Ahi + base)     = __halves2bfloat162(hx, hy);
    *(__nv_bfloat162*)(g_Ahi + base + 2) = __halves2bfloat162(hz, hw);
    *(__nv_bfloat162*)(g_Alo + base)     = __halves2bfloat162(lx, ly);
    *(__nv_bfloat162*)(g_Alo + base + 2) = __halves2bfloat162(lz, lw);
}

// ---------------- Stage C0: fused weight split ----------------
__global__ void build_wb_kernel(const float* __restrict__ wl,
                                const float* __restrict__ wr) {
    int idx = blockIdx.x * blockDim.x + threadIdx.x;   // [0, 128*256)
    if (idx >= 128 * 256) return;
    int n = idx >> 8;
    int k = idx & 255;
    float v = (k < 128) ? wl[n * 128 + k] : wr[n * 128 + (k - 128)];
    __nv_bfloat16 hi, lo;
    split_bf16(v, hi, lo);
    g_Bhi[idx] = hi;
    g_Blo[idx] = lo;
}

// ---------------- Stage C: mma.sync split-bf16 GEMM ----------------
// out = Ahi@Bhi^T + Ahi@Blo^T + Alo@Bhi^T + bias
// SMEM: Bhi [128n][256k] swizzled (64KB), Blo (64KB), A chunk [128m][64k] (16KB)
#define BH_OFF 0
#define BL_OFF 65536
#define AS_OFF 131072
#define GSMEM_TOTAL 147456

__global__ __launch_bounds__(256, 1) void mma_gemm_kernel(const float* __restrict__ bias,
                                                          float* __restrict__ out, int N) {
    extern __shared__ char smem[];
    uint32_t sb = smem_u32(smem);
    int tid = threadIdx.x;
    int lane = tid & 31;
    int wid = tid >> 5;
    int warp_m = wid & 3;        // 4 m-tiles of 32 rows
    int warp_n = wid >> 2;       // 2 n-tiles of 64 cols
    int rowBase = blockIdx.x * 128;

    // stage B hi/lo: [n][k], 16B chunk index XOR-swizzled by (n&7)
    for (int idx = tid; idx < 4096; idx += 256) {
        int r  = idx >> 5;
        int ck = idx & 31;                       // 16B-chunk within row (8 bf16)
        uint32_t off = (uint32_t)r * 512 + ((uint32_t)(ck ^ (r & 7)) << 4);
        *(uint4*)(smem + BH_OFF + off) = *(const uint4*)(g_Bhi + (size_t)r * 256 + ck * 8);
        *(uint4*)(smem + BL_OFF + off) = *(const uint4*)(g_Blo + (size_t)r * 256 + ck * 8);
    }

    float acc[2][8][4];
    #pragma unroll
    for (int i = 0; i < 2; i++)
        #pragma unroll
        for (int j = 0; j < 8; j++)
            #pragma unroll
            for (int q = 0; q < 4; q++) acc[i][j][q] = 0.0f;

    // ldmatrix lane routing
    int aRow = (lane & 7) + ((lane >> 3) & 1) * 8;   // row within 16-row tile
    int aK8  = (lane >> 4) * 8;                      // +0 / +8 in k
    int bN   = (lane & 7) + (lane >> 4) * 8;         // n within 16-col group
    int bK8  = ((lane >> 3) & 1) * 8;

    for (int av = 0; av < 2; ++av) {
        const __nv_bfloat16* Asrc = av ? g_Alo : g_Ahi;
        for (int c = 0; c < 4; ++c) {
            __syncthreads();
            // stage A chunk [128][64], swizzled
            for (int idx = tid; idx < 1024; idx += 256) {
                int r  = idx >> 3;
                int ck = idx & 7;
                uint4 v = *(const uint4*)(Asrc + (size_t)(rowBase + r) * 256 + c * 64 + ck * 8);
                *(uint4*)(smem + AS_OFF + r * 128 + ((uint32_t)(ck ^ (r & 7)) << 4)) = v;
            }
            __syncthreads();
            #pragma unroll
            for (int ks = 0; ks < 4; ++ks) {
                int kk = ks * 16;
                uint32_t a[2][4];
                #pragma unroll
                for (int mf = 0; mf < 2; ++mf) {
                    int row = warp_m * 32 + mf * 16 + aRow;
                    int kA  = kk + aK8;
                    uint32_t addr = sb + AS_OFF + (uint32_t)row * 128
                                  + ((uint32_t)(((kA >> 3) ^ (row & 7))) << 4);
                    ldmat_x4(addr, a[mf]);
                }
                int gk = c * 64 + kk;
                #pragma unroll
                for (int bv = 0; bv < 2; ++bv) {
                    if (av == 1 && bv == 1) continue;   // skip lo*lo
                    uint32_t boff = bv ? BL_OFF : BH_OFF;
                    #pragma unroll
                    for (int j = 0; j < 4; ++j) {
                        int n  = warp_n * 64 + j * 16 + bN;
                        int kB = gk + bK8;
                        uint32_t addr = sb + boff + (uint32_t)n * 512
                                      + ((uint32_t)(((kB >> 3) ^ (n & 7))) << 4);
                        uint32_t b[4];          // {b0(n), b1(n), b0(n+8), b1(n+8)}
                        ldmat_x4(addr, b);
                        mma16816(acc[0][2 * j],     a[0], b[0], b[1]);
                        mma16816(acc[0][2 * j + 1], a[0], b[2], b[3]);
                        mma16816(acc[1][2 * j],     a[1], b[0], b[1]);
                        mma16816(acc[1][2 * j + 1], a[1], b[2], b[3]);
                    }
                }
            }
        }
    }

    // epilogue: bias + store
    float2 bcol[8];
    #pragma unroll
    for (int nf = 0; nf < 8; ++nf) {
        int col = warp_n * 64 + nf * 8 + (lane & 3) * 2;
        bcol[nf] = *(const float2*)(bias + col);
    }
    #pragma unroll
    for (int mf = 0; mf < 2; ++mf) {
        int r0 = rowBase + warp_m * 32 + mf * 16 + (lane >> 2);
        #pragma unroll
        for (int h = 0; h < 2; ++h) {
            int row = r0 + h * 8;
            if (row < N) {
                #pragma unroll
                for (int nf = 0; nf < 8; ++nf) {
                    int col = warp_n * 64 + nf * 8 + (lane & 3) * 2;
                    float2 o;
                    o.x = acc[mf][nf][h * 2 + 0] + bcol[nf].x;
                    o.y = acc[mf][nf][h * 2 + 1] + bcol[nf].y;
                    *(float2*)(out + (size_t)row * D + col) = o;
                }
            }
        }
    }
}

// ---------------- launch ----------------
extern "C" void kernel_launch(void* const* d_in, const int* in_sizes, int n_in,
                              void* d_out, int out_size) {
    const float* x     = (const float*)d_in[0];
    const void*  edges =               d_in[1];
    const float* mask  = (const float*)d_in[2];
    const float* gamma = (const float*)d_in[3];
    const float* beta  = (const float*)d_in[4];
    const float* wl    = (const float*)d_in[5];
    const float* bl    = (const float*)d_in[6];
    const float* wr    = (const float*)d_in[7];
    float* out = (float*)d_out;

    int N = in_sizes[0] / D;
    int E = in_sizes[1] / 2;

    cudaFuncSetAttribute(mma_gemm_kernel,
                         cudaFuncAttributeMaxDynamicSharedMemorySize, GSMEM_TOTAL);

    int nwords = E < 2048 ? E : 2048;
    detect_dtype_kernel<<<1, 1024>>>((const unsigned long long*)edges, nwords,
                                     (unsigned long long)N);

    ln_relu_mask_kernel<<<(N + 7) / 8, 256>>>(x, mask, gamma, beta, N);

    zero_deg_kernel<<<(N + 255) / 256, 256>>>(N);
    count_deg_kernel<<<1024, 256>>>(edges, E);
    int nb = (N + 1023) / 1024;
    scan1_kernel<<<nb, 1024>>>(N);
    scan2_kernel<<<1, 1024>>>(nb);
    add_offsets_kernel<<<(N + 255) / 256, 256>>>(N);
    scatter_kernel<<<1024, 256>>>(edges, E);

    aggregate_kernel<<<(N + 7) / 8, 256>>>(N);

    build_wb_kernel<<<(128 * 256 + 255) / 256, 256>>>(wl, wr);
    mma_gemm_kernel<<<(N + 127) / 128, 256, GSMEM_TOTAL>>>(bl, out, N);
}

// round 4
// speedup vs baseline: 1.7342x; 1.6681x over previous
#include <cuda_runtime.h>
#include <cuda_bf16.h>
#include <cuda_fp16.h>
#include <cstdint>

// ---------------- problem-size constants ----------------
#define MAX_N 50176
#define MAX_E 800000
#define D 128

// ---------------- device scratch ----------------
// A matrix for GEMM, fp16: cols [0,128) = agg, cols [128,256) = h
__device__ __half g_A[(size_t)MAX_N * 256];
__device__ __half g_W[128 * 256];            // fused weights [n][k] fp16
__device__ int   g_deg[MAX_N];
__device__ int   g_start[MAX_N];
__device__ int   g_cursor[MAX_N];
__device__ int   g_csr[MAX_E];
__device__ int   g_bsums[1024];
__device__ int   g_is32;

// ---------------- helpers ----------------
__device__ __forceinline__ uint32_t smem_u32(const void* p) {
    uint32_t a;
    asm("{ .reg .u64 t; cvta.to.shared.u64 t, %1; cvt.u32.u64 %0, t; }" : "=r"(a) : "l"(p));
    return a;
}

__device__ __forceinline__ void ldmat_x4(uint32_t addr, uint32_t* r) {
    asm volatile("ldmatrix.sync.aligned.m8n8.x4.shared.b16 {%0,%1,%2,%3}, [%4];"
                 : "=r"(r[0]), "=r"(r[1]), "=r"(r[2]), "=r"(r[3]) : "r"(addr));
}

__device__ __forceinline__ void mma16816(float* d, const uint32_t* a,
                                         uint32_t b0, uint32_t b1) {
    asm volatile(
        "mma.sync.aligned.m16n8k16.row.col.f32.f16.f16.f32 "
        "{%0,%1,%2,%3}, {%4,%5,%6,%7}, {%8,%9}, {%0,%1,%2,%3};"
        : "+f"(d[0]), "+f"(d[1]), "+f"(d[2]), "+f"(d[3])
        : "r"(a[0]), "r"(a[1]), "r"(a[2]), "r"(a[3]), "r"(b0), "r"(b1));
}

__device__ __forceinline__ int edge_at(const void* p, long long idx, int is32) {
    if (is32) return ((const int*)p)[idx];
    return (int)((const long long*)p)[idx];
}

// ---------------- init: zero degrees + edge dtype detection ----------------
__global__ void init_kernel(const unsigned long long* __restrict__ e,
                            int nwords, unsigned long long Nval, int N) {
    int i = blockIdx.x * blockDim.x + threadIdx.x;
    if (i < N) g_deg[i] = 0;
    if (blockIdx.x == 0) {
        int bad = 0;
        for (int j = threadIdx.x; j < nwords; j += blockDim.x)
            if (e[j] >= Nval) bad = 1;
        bad = __syncthreads_or(bad);
        if (threadIdx.x == 0) g_is32 = bad;
    }
}

// ---------------- Stage A: LayerNorm + ReLU + dropout -> fp16 h ----------------
__global__ void ln_relu_mask_kernel(const float* __restrict__ x,
                                    const float* __restrict__ mask,
                                    const float* __restrict__ gamma,
                                    const float* __restrict__ beta,
                                    int N) {
    int warp = (blockIdx.x * blockDim.x + threadIdx.x) >> 5;
    int lane = threadIdx.x & 31;
    if (warp >= N) return;
    const float4* xr = (const float4*)(x + (size_t)warp * D);
    float4 v = xr[lane];
    float s  = v.x + v.y + v.z + v.w;
    float ss = v.x * v.x + v.y * v.y + v.z * v.z + v.w * v.w;
    #pragma unroll
    for (int o = 16; o; o >>= 1) {
        s  += __shfl_xor_sync(0xffffffffu, s,  o);
        ss += __shfl_xor_sync(0xffffffffu, ss, o);
    }
    float mu  = s * (1.0f / D);
    float var = ss * (1.0f / D) - mu * mu;
    float inv = rsqrtf(var + 1e-5f);
    float4 g = ((const float4*)gamma)[lane];
    float4 b = ((const float4*)beta)[lane];
    float4 m = ((const float4*)(mask + (size_t)warp * D))[lane];
    float2 p0, p1;
    p0.x = fmaxf((v.x - mu) * inv * g.x + b.x, 0.0f) * m.x;
    p0.y = fmaxf((v.y - mu) * inv * g.y + b.y, 0.0f) * m.y;
    p1.x = fmaxf((v.z - mu) * inv * g.z + b.z, 0.0f) * m.z;
    p1.y = fmaxf((v.w - mu) * inv * g.w + b.w, 0.0f) * m.w;
    __half2* dst = (__half2*)(g_A + (size_t)warp * 256 + 128 + lane * 4);
    dst[0] = __float22half2_rn(p0);
    dst[1] = __float22half2_rn(p1);
}

// ---------------- Stage B: CSR build ----------------
__global__ void count_deg_kernel(const void* __restrict__ edges, int E) {
    int is32 = g_is32;
    for (long long e = blockIdx.x * (long long)blockDim.x + threadIdx.x;
         e < E; e += (long long)gridDim.x * blockDim.x) {
        int dst = edge_at(edges, (long long)E + e, is32);
        atomicAdd(&g_deg[dst], 1);
    }
}

__global__ void scan1_kernel(int N) {
    __shared__ int sh[1024];
    int i = blockIdx.x * 1024 + threadIdx.x;
    int v = (i < N) ? g_deg[i] : 0;
    sh[threadIdx.x] = v;
    __syncthreads();
    #pragma unroll
    for (int off = 1; off < 1024; off <<= 1) {
        int t = (threadIdx.x >= off) ? sh[threadIdx.x - off] : 0;
        __syncthreads();
        sh[threadIdx.x] += t;
        __syncthreads();
    }
    if (i < N) g_start[i] = sh[threadIdx.x] - v;
    if (threadIdx.x == 1023) g_bsums[blockIdx.x] = sh[1023];
}

__global__ void scan2_kernel(int nb) {
    __shared__ int sh[1024];
    int v = (threadIdx.x < nb) ? g_bsums[threadIdx.x] : 0;
    sh[threadIdx.x] = v;
    __syncthreads();
    #pragma unroll
    for (int off = 1; off < 1024; off <<= 1) {
        int t = (threadIdx.x >= off) ? sh[threadIdx.x - off] : 0;
        __syncthreads();
        sh[threadIdx.x] += t;
        __syncthreads();
    }
    if (threadIdx.x < nb) g_bsums[threadIdx.x] = sh[threadIdx.x] - v;
}

__global__ void add_offsets_kernel(int N) {
    int i = blockIdx.x * blockDim.x + threadIdx.x;
    if (i < N) {
        int s = g_start[i] + g_bsums[i >> 10];
        g_start[i] = s;
        g_cursor[i] = s;
    }
}

__global__ void scatter_kernel(const void* __restrict__ edges, int E) {
    int is32 = g_is32;
    for (long long e = blockIdx.x * (long long)blockDim.x + threadIdx.x;
         e < E; e += (long long)gridDim.x * blockDim.x) {
        int src = edge_at(edges, e, is32);
        int dst = edge_at(edges, (long long)E + e, is32);
        int pos = atomicAdd(&g_cursor[dst], 1);
        g_csr[pos] = src;
    }
}

// ---------------- Stage B4: mean aggregation (fp16 in, fp16 out) ----------
__global__ void aggregate_kernel(int N) {
    int warp = (blockIdx.x * blockDim.x + threadIdx.x) >> 5;
    int lane = threadIdx.x & 31;
    if (warp >= N) return;
    int st = g_start[warp];
    int d  = g_deg[warp];
    float2 acc0 = make_float2(0.f, 0.f);
    float2 acc1 = make_float2(0.f, 0.f);
    int j = st, end = st + d;
    for (; j + 4 <= end; j += 4) {
        int s0 = g_csr[j], s1 = g_csr[j + 1], s2 = g_csr[j + 2], s3 = g_csr[j + 3];
        const __half2* r0 = (const __half2*)(g_A + (size_t)s0 * 256 + 128 + lane * 4);
        const __half2* r1 = (const __half2*)(g_A + (size_t)s1 * 256 + 128 + lane * 4);
        const __half2* r2 = (const __half2*)(g_A + (size_t)s2 * 256 + 128 + lane * 4);
        const __half2* r3 = (const __half2*)(g_A + (size_t)s3 * 256 + 128 + lane * 4);
        float2 a, b;
        a = __half22float2(r0[0]); b = __half22float2(r0[1]);
        acc0.x += a.x; acc0.y += a.y; acc1.x += b.x; acc1.y += b.y;
        a = __half22float2(r1[0]); b = __half22float2(r1[1]);
        acc0.x += a.x; acc0.y += a.y; acc1.x += b.x; acc1.y += b.y;
        a = __half22float2(r2[0]); b = __half22float2(r2[1]);
        acc0.x += a.x; acc0.y += a.y; acc1.x += b.x; acc1.y += b.y;
        a = __half22float2(r3[0]); b = __half22float2(r3[1]);
        acc0.x += a.x; acc0.y += a.y; acc1.x += b.x; acc1.y += b.y;
    }
    for (; j < end; ++j) {
        int s0 = g_csr[j];
        const __half2* r0 = (const __half2*)(g_A + (size_t)s0 * 256 + 128 + lane * 4);
        float2 a = __half22float2(r0[0]);
        float2 b = __half22float2(r0[1]);
        acc0.x += a.x; acc0.y += a.y; acc1.x += b.x; acc1.y += b.y;
    }
    float invd = 1.0f / fmaxf((float)d, 1.0f);
    acc0.x *= invd; acc0.y *= invd; acc1.x *= invd; acc1.y *= invd;
    __half2* dst = (__half2*)(g_A + (size_t)warp * 256 + lane * 4);
    dst[0] = __float22half2_rn(acc0);
    dst[1] = __float22half2_rn(acc1);
}

// ---------------- Stage C0: fused fp16 weights ----------------
__global__ void build_w_kernel(const float* __restrict__ wl,
                               const float* __restrict__ wr) {
    int idx = blockIdx.x * blockDim.x + threadIdx.x;   // [0, 128*256)
    if (idx >= 128 * 256) return;
    int n = idx >> 8;
    int k = idx & 255;
    float v = (k < 128) ? wl[n * 128 + k] : wr[n * 128 + (k - 128)];
    g_W[idx] = __float2half_rn(v);
}

// ---------------- Stage C: fp16 mma GEMM, single pass ----------------
// out = A @ W^T + bias   (A [N][256] fp16, W [128][256] fp16)
#define B_OFF 0
#define A_OFF 65536
#define GSMEM_TOTAL 81920

__global__ __launch_bounds__(256) void mma_gemm_kernel(const float* __restrict__ bias,
                                                       float* __restrict__ out, int N) {
    extern __shared__ char smem[];
    uint32_t sb = smem_u32(smem);
    int tid = threadIdx.x;
    int lane = tid & 31;
    int wid = tid >> 5;
    int warp_m = wid & 3;        // 4 m-tiles of 32 rows
    int warp_n = wid >> 2;       // 2 n-tiles of 64 cols
    int rowBase = blockIdx.x * 128;

    // stage W: [n][k] fp16, 16B chunks, XOR-swizzled by (n&7)
    for (int idx = tid; idx < 4096; idx += 256) {
        int r  = idx >> 5;
        int ck = idx & 31;
        uint32_t off = (uint32_t)r * 512 + ((uint32_t)(ck ^ (r & 7)) << 4);
        *(uint4*)(smem + B_OFF + off) = *(const uint4*)(g_W + (size_t)r * 256 + ck * 8);
    }

    float acc[2][8][4];
    #pragma unroll
    for (int i = 0; i < 2; i++)
        #pragma unroll
        for (int j = 0; j < 8; j++)
            #pragma unroll
            for (int q = 0; q < 4; q++) acc[i][j][q] = 0.0f;

    // ldmatrix lane routing
    int aRow = (lane & 7) + ((lane >> 3) & 1) * 8;
    int aK8  = (lane >> 4) * 8;
    int bN   = (lane & 7) + (lane >> 4) * 8;
    int bK8  = ((lane >> 3) & 1) * 8;

    for (int c = 0; c < 4; ++c) {
        if (c) __syncthreads();
        // stage A chunk [128][64] fp16, swizzled
        for (int idx = tid; idx < 1024; idx += 256) {
            int r  = idx >> 3;
            int ck = idx & 7;
            uint4 v = *(const uint4*)(g_A + (size_t)(rowBase + r) * 256 + c * 64 + ck * 8);
            *(uint4*)(smem + A_OFF + r * 128 + ((uint32_t)(ck ^ (r & 7)) << 4)) = v;
        }
        __syncthreads();
        #pragma unroll
        for (int ks = 0; ks < 4; ++ks) {
            int kk = ks * 16;
            uint32_t a[2][4];
            #pragma unroll
            for (int mf = 0; mf < 2; ++mf) {
                int row = warp_m * 32 + mf * 16 + aRow;
                int kA  = kk + aK8;
                uint32_t addr = sb + A_OFF + (uint32_t)row * 128
                              + ((uint32_t)(((kA >> 3) ^ (row & 7))) << 4);
                ldmat_x4(addr, a[mf]);
            }
            int gk = c * 64 + kk;
            #pragma unroll
            for (int j = 0; j < 4; ++j) {
                int n  = warp_n * 64 + j * 16 + bN;
                int kB = gk + bK8;
                uint32_t addr = sb + B_OFF + (uint32_t)n * 512
                              + ((uint32_t)(((kB >> 3) ^ (n & 7))) << 4);
                uint32_t b[4];
                ldmat_x4(addr, b);
                mma16816(acc[0][2 * j],     a[0], b[0], b[1]);
                mma16816(acc[0][2 * j + 1], a[0], b[2], b[3]);
                mma16816(acc[1][2 * j],     a[1], b[0], b[1]);
                mma16816(acc[1][2 * j + 1], a[1], b[2], b[3]);
            }
        }
    }

    // epilogue: bias + store
    float2 bcol[8];
    #pragma unroll
    for (int nf = 0; nf < 8; ++nf) {
        int col = warp_n * 64 + nf * 8 + (lane & 3) * 2;
        bcol[nf] = *(const float2*)(bias + col);
    }
    #pragma unroll
    for (int mf = 0; mf < 2; ++mf) {
        int r0 = rowBase + warp_m * 32 + mf * 16 + (lane >> 2);
        #pragma unroll
        for (int h = 0; h < 2; ++h) {
            int row = r0 + h * 8;
            if (row < N) {
                #pragma unroll
                for (int nf = 0; nf < 8; ++nf) {
                    int col = warp_n * 64 + nf * 8 + (lane & 3) * 2;
                    float2 o;
                    o.x = acc[mf][nf][h * 2 + 0] + bcol[nf].x;
                    o.y = acc[mf][nf][h * 2 + 1] + bcol[nf].y;
                    *(float2*)(out + (size_t)row * D + col) = o;
                }
            }
        }
    }
}

// ---------------- launch ----------------
extern "C" void kernel_launch(void* const* d_in, const int* in_sizes, int n_in,
                              void* d_out, int out_size) {
    const float* x     = (const float*)d_in[0];
    const void*  edges =               d_in[1];
    const float* mask  = (const float*)d_in[2];
    const float* gamma = (const float*)d_in[3];
    const float* beta  = (const float*)d_in[4];
    const float* wl    = (const float*)d_in[5];
    const float* bl    = (const float*)d_in[6];
    const float* wr    = (const float*)d_in[7];
    float* out = (float*)d_out;

    int N = in_sizes[0] / D;
    int E = in_sizes[1] / 2;

    cudaFuncSetAttribute(mma_gemm_kernel,
                         cudaFuncAttributeMaxDynamicSharedMemorySize, GSMEM_TOTAL);

    int nwords = E < 2048 ? E : 2048;
    init_kernel<<<(N + 1023) / 1024, 1024>>>((const unsigned long long*)edges,
                                             nwords, (unsigned long long)N, N);

    ln_relu_mask_kernel<<<(N + 7) / 8, 256>>>(x, mask, gamma, beta, N);

    count_deg_kernel<<<1024, 256>>>(edges, E);
    int nb = (N + 1023) / 1024;
    scan1_kernel<<<nb, 1024>>>(N);
    scan2_kernel<<<1, 1024>>>(nb);
    add_offsets_kernel<<<(N + 255) / 256, 256>>>(N);
    scatter_kernel<<<1024, 256>>>(edges, E);

    aggregate_kernel<<<(N + 7) / 8, 256>>>(N);

    build_w_kernel<<<(128 * 256 + 255) / 256, 256>>>(wl, wr);
    mma_gemm_kernel<<<(N + 127) / 128, 256, GSMEM_TOTAL>>>(bl, out, N);
}

// round 5
// speedup vs baseline: 1.8213x; 1.0502x over previous
#include <cuda_runtime.h>
#include <cuda_bf16.h>
#include <cuda_fp16.h>
#include <cstdint>

// ---------------- problem-size constants ----------------
#define MAX_N 50176
#define MAX_E 800000
#define D 128

// ---------------- device scratch ----------------
// A matrix for GEMM, fp16: cols [0,128) = agg, cols [128,256) = h
__device__ __half g_A[(size_t)MAX_N * 256];
__device__ __half g_W[128 * 256];            // fused weights [n][k] fp16
__device__ int   g_deg[MAX_N];
__device__ int   g_start[MAX_N];
__device__ int   g_cursor[MAX_N];
__device__ int   g_csr[MAX_E];
__device__ int   g_bsums[256];
__device__ int   g_is32;

// ---------------- helpers ----------------
__device__ __forceinline__ uint32_t smem_u32(const void* p) {
    uint32_t a;
    asm("{ .reg .u64 t; cvta.to.shared.u64 t, %1; cvt.u32.u64 %0, t; }" : "=r"(a) : "l"(p));
    return a;
}

__device__ __forceinline__ void ldmat_x4(uint32_t addr, uint32_t* r) {
    asm volatile("ldmatrix.sync.aligned.m8n8.x4.shared.b16 {%0,%1,%2,%3}, [%4];"
                 : "=r"(r[0]), "=r"(r[1]), "=r"(r[2]), "=r"(r[3]) : "r"(addr));
}

__device__ __forceinline__ void mma16816(float* d, const uint32_t* a,
                                         uint32_t b0, uint32_t b1) {
    asm volatile(
        "mma.sync.aligned.m16n8k16.row.col.f32.f16.f16.f32 "
        "{%0,%1,%2,%3}, {%4,%5,%6,%7}, {%8,%9}, {%0,%1,%2,%3};"
        : "+f"(d[0]), "+f"(d[1]), "+f"(d[2]), "+f"(d[3])
        : "r"(a[0]), "r"(a[1]), "r"(a[2]), "r"(a[3]), "r"(b0), "r"(b1));
}

// ---------------- edge dtype detection ----------------
__global__ void detect_dtype_kernel(const unsigned long long* __restrict__ e,
                                    int nwords, unsigned long long Nval) {
    int bad = 0;
    for (int j = threadIdx.x; j < nwords; j += blockDim.x)
        if (e[j] >= Nval) bad = 1;
    bad = __syncthreads_or(bad);
    if (threadIdx.x == 0) g_is32 = bad;
}

// ---------------- Stage A: LayerNorm + ReLU + dropout -> fp16 ----------------
__global__ void ln_relu_mask_kernel(const float* __restrict__ x,
                                    const float* __restrict__ mask,
                                    const float* __restrict__ gamma,
                                    const float* __restrict__ beta,
                                    int N) {
    int warp = (blockIdx.x * blockDim.x + threadIdx.x) >> 5;
    int lane = threadIdx.x & 31;
    if (warp >= N) return;
    const float4* xr = (const float4*)(x + (size_t)warp * D);
    float4 v = xr[lane];
    float s  = v.x + v.y + v.z + v.w;
    float ss = v.x * v.x + v.y * v.y + v.z * v.z + v.w * v.w;
    #pragma unroll
    for (int o = 16; o; o >>= 1) {
        s  += __shfl_xor_sync(0xffffffffu, s,  o);
        ss += __shfl_xor_sync(0xffffffffu, ss, o);
    }
    float mu  = s * (1.0f / D);
    float var = ss * (1.0f / D) - mu * mu;
    float inv = rsqrtf(var + 1e-5f);
    float4 g = ((const float4*)gamma)[lane];
    float4 b = ((const float4*)beta)[lane];
    float4 m = ((const float4*)(mask + (size_t)warp * D))[lane];
    float2 p0, p1;
    p0.x = fmaxf((v.x - mu) * inv * g.x + b.x, 0.0f) * m.x;
    p0.y = fmaxf((v.y - mu) * inv * g.y + b.y, 0.0f) * m.y;
    p1.x = fmaxf((v.z - mu) * inv * g.z + b.z, 0.0f) * m.z;
    p1.y = fmaxf((v.w - mu) * inv * g.w + b.w, 0.0f) * m.w;
    __half2* dst = (__half2*)(g_A + (size_t)warp * 256 + 128 + lane * 4);
    dst[0] = __float22half2_rn(p0);
    dst[1] = __float22half2_rn(p1);
}

// ---------------- Stage B1: degree count (vectorized) ----------------
__global__ void count_deg_kernel(const void* __restrict__ edges, int E) {
    long long gtid = blockIdx.x * (long long)blockDim.x + threadIdx.x;
    long long stride = (long long)gridDim.x * blockDim.x;
    if (g_is32) {
        const int* dst = (const int*)edges + E;
        const int4* d4 = (const int4*)dst;
        int n4 = E >> 2;
        for (long long i = gtid; i < n4; i += stride) {
            int4 v = d4[i];
            atomicAdd(&g_deg[v.x], 1);
            atomicAdd(&g_deg[v.y], 1);
            atomicAdd(&g_deg[v.z], 1);
            atomicAdd(&g_deg[v.w], 1);
        }
        int tail = E & 3;
        if (gtid < tail) atomicAdd(&g_deg[dst[(E & ~3) + (int)gtid]], 1);
    } else {
        const long long* dst = (const long long*)edges + E;
        const longlong2* d2 = (const longlong2*)dst;
        int n2 = E >> 1;
        for (long long i = gtid; i < n2; i += stride) {
            longlong2 v = d2[i];
            atomicAdd(&g_deg[(int)v.x], 1);
            atomicAdd(&g_deg[(int)v.y], 1);
        }
        if ((E & 1) && gtid == 0) atomicAdd(&g_deg[(int)dst[E - 1]], 1);
    }
}

// ---------------- Stage B2: scan (shfl-based) ----------------
__global__ void scan1_kernel(int N) {
    __shared__ int ws[32];
    int i = blockIdx.x * 1024 + threadIdx.x;
    int lane = threadIdx.x & 31, wid = threadIdx.x >> 5;
    int v = (i < N) ? g_deg[i] : 0;
    int incl = v;
    #pragma unroll
    for (int o = 1; o < 32; o <<= 1) {
        int t = __shfl_up_sync(0xffffffffu, incl, o);
        if (lane >= o) incl += t;
    }
    if (lane == 31) ws[wid] = incl;
    __syncthreads();
    if (wid == 0) {
        int sv = ws[lane];
        int in2 = sv;
        #pragma unroll
        for (int o = 1; o < 32; o <<= 1) {
            int t = __shfl_up_sync(0xffffffffu, in2, o);
            if (lane >= o) in2 += t;
        }
        ws[lane] = in2 - sv;   // exclusive warp prefix
    }
    __syncthreads();
    int excl = incl - v + ws[wid];
    if (i < N) g_start[i] = excl;
    if (threadIdx.x == 1023) g_bsums[blockIdx.x] = excl + v;
}

// block-prefix of bsums computed in-kernel (nb <= 64)
__global__ void add_offsets_kernel(int N) {
    __shared__ int tmp[32];
    __shared__ int pref;
    int b = blockIdx.x;
    int lane = threadIdx.x & 31, wid = threadIdx.x >> 5;
    int s = (threadIdx.x < b) ? g_bsums[threadIdx.x] : 0;   // b <= 64 < 1024
    #pragma unroll
    for (int o = 16; o; o >>= 1) s += __shfl_xor_sync(0xffffffffu, s, o);
    if (lane == 0) tmp[wid] = s;
    __syncthreads();
    if (threadIdx.x == 0) {
        int t = 0;
        #pragma unroll
        for (int w = 0; w < 32; ++w) t += tmp[w];
        pref = t;
    }
    __syncthreads();
    int i = b * 1024 + threadIdx.x;
    if (i < N) {
        int st = g_start[i] + pref;
        g_start[i] = st;
        g_cursor[i] = st;
    }
}

// ---------------- Stage B3: scatter (vectorized) ----------------
__global__ void scatter_kernel(const void* __restrict__ edges, int E) {
    long long gtid = blockIdx.x * (long long)blockDim.x + threadIdx.x;
    long long stride = (long long)gridDim.x * blockDim.x;
    if (g_is32) {
        const int4* s4 = (const int4*)edges;
        const int4* d4 = (const int4*)((const int*)edges + E);
        int n4 = E >> 2;
        for (long long i = gtid; i < n4; i += stride) {
            int4 sv = s4[i];
            int4 dv = d4[i];
            g_csr[atomicAdd(&g_cursor[dv.x], 1)] = sv.x;
            g_csr[atomicAdd(&g_cursor[dv.y], 1)] = sv.y;
            g_csr[atomicAdd(&g_cursor[dv.z], 1)] = sv.z;
            g_csr[atomicAdd(&g_cursor[dv.w], 1)] = sv.w;
        }
        int tail = E & 3;
        if (gtid < tail) {
            int e = (E & ~3) + (int)gtid;
            int src = ((const int*)edges)[e];
            int dst = ((const int*)edges)[E + e];
            g_csr[atomicAdd(&g_cursor[dst], 1)] = src;
        }
    } else {
        const longlong2* s2 = (const longlong2*)edges;
        const longlong2* d2 = (const longlong2*)((const long long*)edges + E);
        int n2 = E >> 1;
        for (long long i = gtid; i < n2; i += stride) {
            longlong2 sv = s2[i];
            longlong2 dv = d2[i];
            g_csr[atomicAdd(&g_cursor[(int)dv.x], 1)] = (int)sv.x;
            g_csr[atomicAdd(&g_cursor[(int)dv.y], 1)] = (int)sv.y;
        }
        if ((E & 1) && gtid == 0) {
            int src = (int)((const long long*)edges)[E - 1];
            int dst = (int)((const long long*)edges)[2 * E - 1];
            g_csr[atomicAdd(&g_cursor[dst], 1)] = src;
        }
    }
}

// ---------------- Stage B4: mean aggregation (fp16 in, fp16 out) ----------
__global__ void aggregate_kernel(int N) {
    int warp = (blockIdx.x * blockDim.x + threadIdx.x) >> 5;
    int lane = threadIdx.x & 31;
    if (warp >= N) return;
    int st = g_start[warp];
    int d  = g_deg[warp];
    float2 acc0 = make_float2(0.f, 0.f);
    float2 acc1 = make_float2(0.f, 0.f);
    int j = st, end = st + d;
    for (; j + 4 <= end; j += 4) {
        int s0 = g_csr[j], s1 = g_csr[j + 1], s2 = g_csr[j + 2], s3 = g_csr[j + 3];
        const __half2* r0 = (const __half2*)(g_A + (size_t)s0 * 256 + 128 + lane * 4);
        const __half2* r1 = (const __half2*)(g_A + (size_t)s1 * 256 + 128 + lane * 4);
        const __half2* r2 = (const __half2*)(g_A + (size_t)s2 * 256 + 128 + lane * 4);
        const __half2* r3 = (const __half2*)(g_A + (size_t)s3 * 256 + 128 + lane * 4);
        float2 a, b;
        a = __half22float2(r0[0]); b = __half22float2(r0[1]);
        acc0.x += a.x; acc0.y += a.y; acc1.x += b.x; acc1.y += b.y;
        a = __half22float2(r1[0]); b = __half22float2(r1[1]);
        acc0.x += a.x; acc0.y += a.y; acc1.x += b.x; acc1.y += b.y;
        a = __half22float2(r2[0]); b = __half22float2(r2[1]);
        acc0.x += a.x; acc0.y += a.y; acc1.x += b.x; acc1.y += b.y;
        a = __half22float2(r3[0]); b = __half22float2(r3[1]);
        acc0.x += a.x; acc0.y += a.y; acc1.x += b.x; acc1.y += b.y;
    }
    for (; j < end; ++j) {
        int s0 = g_csr[j];
        const __half2* r0 = (const __half2*)(g_A + (size_t)s0 * 256 + 128 + lane * 4);
        float2 a = __half22float2(r0[0]);
        float2 b = __half22float2(r0[1]);
        acc0.x += a.x; acc0.y += a.y; acc1.x += b.x; acc1.y += b.y;
    }
    float invd = 1.0f / fmaxf((float)d, 1.0f);
    acc0.x *= invd; acc0.y *= invd; acc1.x *= invd; acc1.y *= invd;
    __half2* dst = (__half2*)(g_A + (size_t)warp * 256 + lane * 4);
    dst[0] = __float22half2_rn(acc0);
    dst[1] = __float22half2_rn(acc1);
}

// ---------------- Stage C0: fused fp16 weights ----------------
__global__ void build_w_kernel(const float* __restrict__ wl,
                               const float* __restrict__ wr) {
    int idx = blockIdx.x * blockDim.x + threadIdx.x;
    if (idx >= 128 * 256) return;
    int n = idx >> 8;
    int k = idx & 255;
    float v = (k < 128) ? wl[n * 128 + k] : wr[n * 128 + (k - 128)];
    g_W[idx] = __float2half_rn(v);
}

// ---------------- Stage C: fp16 mma GEMM, single pass ----------------
#define B_OFF 0
#define A_OFF 65536
#define GSMEM_TOTAL 81920

__global__ __launch_bounds__(256) void mma_gemm_kernel(const float* __restrict__ bias,
                                                       float* __restrict__ out, int N) {
    extern __shared__ char smem[];
    uint32_t sb = smem_u32(smem);
    int tid = threadIdx.x;
    int lane = tid & 31;
    int wid = tid >> 5;
    int warp_m = wid & 3;
    int warp_n = wid >> 2;
    int rowBase = blockIdx.x * 128;

    for (int idx = tid; idx < 4096; idx += 256) {
        int r  = idx >> 5;
        int ck = idx & 31;
        uint32_t off = (uint32_t)r * 512 + ((uint32_t)(ck ^ (r & 7)) << 4);
        *(uint4*)(smem + B_OFF + off) = *(const uint4*)(g_W + (size_t)r * 256 + ck * 8);
    }

    float acc[2][8][4];
    #pragma unroll
    for (int i = 0; i < 2; i++)
        #pragma unroll
        for (int j = 0; j < 8; j++)
            #pragma unroll
            for (int q = 0; q < 4; q++) acc[i][j][q] = 0.0f;

    int aRow = (lane & 7) + ((lane >> 3) & 1) * 8;
    int aK8  = (lane >> 4) * 8;
    int bN   = (lane & 7) + (lane >> 4) * 8;
    int bK8  = ((lane >> 3) & 1) * 8;

    for (int c = 0; c < 4; ++c) {
        if (c) __syncthreads();
        for (int idx = tid; idx < 1024; idx += 256) {
            int r  = idx >> 3;
            int ck = idx & 7;
            uint4 v = *(const uint4*)(g_A + (size_t)(rowBase + r) * 256 + c * 64 + ck * 8);
            *(uint4*)(smem + A_OFF + r * 128 + ((uint32_t)(ck ^ (r & 7)) << 4)) = v;
        }
        __syncthreads();
        #pragma unroll
        for (int ks = 0; ks < 4; ++ks) {
            int kk = ks * 16;
            uint32_t a[2][4];
            #pragma unroll
            for (int mf = 0; mf < 2; ++mf) {
                int row = warp_m * 32 + mf * 16 + aRow;
                int kA  = kk + aK8;
                uint32_t addr = sb + A_OFF + (uint32_t)row * 128
                              + ((uint32_t)(((kA >> 3) ^ (row & 7))) << 4);
                ldmat_x4(addr, a[mf]);
            }
            int gk = c * 64 + kk;
            #pragma unroll
            for (int j = 0; j < 4; ++j) {
                int n  = warp_n * 64 + j * 16 + bN;
                int kB = gk + bK8;
                uint32_t addr = sb + B_OFF + (uint32_t)n * 512
                              + ((uint32_t)(((kB >> 3) ^ (n & 7))) << 4);
                uint32_t b[4];
                ldmat_x4(addr, b);
                mma16816(acc[0][2 * j],     a[0], b[0], b[1]);
                mma16816(acc[0][2 * j + 1], a[0], b[2], b[3]);
                mma16816(acc[1][2 * j],     a[1], b[0], b[1]);
                mma16816(acc[1][2 * j + 1], a[1], b[2], b[3]);
            }
        }
    }

    float2 bcol[8];
    #pragma unroll
    for (int nf = 0; nf < 8; ++nf) {
        int col = warp_n * 64 + nf * 8 + (lane & 3) * 2;
        bcol[nf] = *(const float2*)(bias + col);
    }
    #pragma unroll
    for (int mf = 0; mf < 2; ++mf) {
        int r0 = rowBase + warp_m * 32 + mf * 16 + (lane >> 2);
        #pragma unroll
        for (int h = 0; h < 2; ++h) {
            int row = r0 + h * 8;
            if (row < N) {
                #pragma unroll
                for (int nf = 0; nf < 8; ++nf) {
                    int col = warp_n * 64 + nf * 8 + (lane & 3) * 2;
                    float2 o;
                    o.x = acc[mf][nf][h * 2 + 0] + bcol[nf].x;
                    o.y = acc[mf][nf][h * 2 + 1] + bcol[nf].y;
                    *(float2*)(out + (size_t)row * D + col) = o;
                }
            }
        }
    }
}

// ---------------- launch ----------------
extern "C" void kernel_launch(void* const* d_in, const int* in_sizes, int n_in,
                              void* d_out, int out_size) {
    const float* x     = (const float*)d_in[0];
    const void*  edges =               d_in[1];
    const float* mask  = (const float*)d_in[2];
    const float* gamma = (const float*)d_in[3];
    const float* beta  = (const float*)d_in[4];
    const float* wl    = (const float*)d_in[5];
    const float* bl    = (const float*)d_in[6];
    const float* wr    = (const float*)d_in[7];
    float* out = (float*)d_out;

    int N = in_sizes[0] / D;
    int E = in_sizes[1] / 2;

    // one-time host-side setup (streams/events are not device memory)
    static cudaStream_t s2 = nullptr;
    static cudaEvent_t evRoot = nullptr, evB = nullptr;
    static int* deg_ptr = nullptr;
    if (!s2) {
        cudaStreamCreateWithFlags(&s2, cudaStreamNonBlocking);
        cudaEventCreateWithFlags(&evRoot, cudaEventDisableTiming);
        cudaEventCreateWithFlags(&evB, cudaEventDisableTiming);
        cudaGetSymbolAddress((void**)&deg_ptr, g_deg);
        cudaFuncSetAttribute(mma_gemm_kernel,
                             cudaFuncAttributeMaxDynamicSharedMemorySize, GSMEM_TOTAL);
    }

    int nb = (N + 1023) / 1024;
    int nwords = E < 2048 ? E : 2048;

    // fork: CSR-build chain on s2
    cudaEventRecord(evRoot, 0);
    cudaStreamWaitEvent(s2, evRoot, 0);
    cudaMemsetAsync(deg_ptr, 0, (size_t)N * sizeof(int), s2);
    detect_dtype_kernel<<<1, 1024, 0, s2>>>((const unsigned long long*)edges,
                                            nwords, (unsigned long long)N);
    count_deg_kernel<<<512, 256, 0, s2>>>(edges, E);
    scan1_kernel<<<nb, 1024, 0, s2>>>(N);
    add_offsets_kernel<<<nb, 1024, 0, s2>>>(N);
    scatter_kernel<<<512, 256, 0, s2>>>(edges, E);
    cudaEventRecord(evB, s2);

    // main stream: LN + weight prep (concurrent with CSR chain)
    ln_relu_mask_kernel<<<(N + 7) / 8, 256>>>(x, mask, gamma, beta, N);
    build_w_kernel<<<(128 * 256 + 255) / 256, 256>>>(wl, wr);

    // join, then aggregate + GEMM
    cudaStreamWaitEvent(0, evB, 0);
    aggregate_kernel<<<(N + 7) / 8, 256>>>(N);
    mma_gemm_kernel<<<(N + 127) / 128, 256, GSMEM_TOTAL>>>(bl, out, N);
}

// round 6
// speedup vs baseline: 2.1977x; 1.2067x over previous
#include <cuda_runtime.h>
#include <cuda_bf16.h>
#include <cuda_fp16.h>
#include <cstdint>

// ---------------- problem-size constants ----------------
#define MAX_N 50176
#define MAX_E 800000
#define D 128

// ---------------- device scratch ----------------
__device__ __half g_A[(size_t)MAX_N * 256];   // cols [0,128)=agg, [128,256)=h
__device__ __half g_W[128 * 256];             // fused weights [n][k] fp16
__device__ int   g_deg[MAX_N];                // zero at kernel-entry invariant
__device__ int   g_start[MAX_N];
__device__ int   g_cursor[MAX_N];
__device__ int   g_csr[MAX_E];
__device__ unsigned long long g_scanState[64]; // lookback: (status<<32)|value
__device__ int   g_is32;

// ---------------- helpers ----------------
__device__ __forceinline__ uint32_t smem_u32(const void* p) {
    uint32_t a;
    asm("{ .reg .u64 t; cvta.to.shared.u64 t, %1; cvt.u32.u64 %0, t; }" : "=r"(a) : "l"(p));
    return a;
}

__device__ __forceinline__ void ldmat_x4(uint32_t addr, uint32_t* r) {
    asm volatile("ldmatrix.sync.aligned.m8n8.x4.shared.b16 {%0,%1,%2,%3}, [%4];"
                 : "=r"(r[0]), "=r"(r[1]), "=r"(r[2]), "=r"(r[3]) : "r"(addr));
}

__device__ __forceinline__ void mma16816(float* d, const uint32_t* a,
                                         uint32_t b0, uint32_t b1) {
    asm volatile(
        "mma.sync.aligned.m16n8k16.row.col.f32.f16.f16.f32 "
        "{%0,%1,%2,%3}, {%4,%5,%6,%7}, {%8,%9}, {%0,%1,%2,%3};"
        : "+f"(d[0]), "+f"(d[1]), "+f"(d[2]), "+f"(d[3])
        : "r"(a[0]), "r"(a[1]), "r"(a[2]), "r"(a[3]), "r"(b0), "r"(b1));
}

#define CP_ASYNC16(dst, src) \
    asm volatile("cp.async.cg.shared.global [%0], [%1], 16;" :: "r"(dst), "l"(src))
#define CP_COMMIT() asm volatile("cp.async.commit_group;")
#define CP_WAIT(n)  asm volatile("cp.async.wait_group %0;" :: "n"(n))

// inline dtype probe: true if buffer is int32 (any of first 64 u64 words >= N)
__device__ __forceinline__ int probe_is32(const void* edges, unsigned long long Nval) {
    const unsigned long long* e = (const unsigned long long*)edges;
    int bad = 0;
    if (threadIdx.x < 64) bad = (e[threadIdx.x] >= Nval);
    return __syncthreads_or(bad);
}

// ---------------- Stage A: LayerNorm + ReLU + dropout -> fp16 ----------------
__global__ void ln_relu_mask_kernel(const float* __restrict__ x,
                                    const float* __restrict__ mask,
                                    const float* __restrict__ gamma,
                                    const float* __restrict__ beta,
                                    int N) {
    int warp = (blockIdx.x * blockDim.x + threadIdx.x) >> 5;
    int lane = threadIdx.x & 31;
    if (warp >= N) return;
    const float4* xr = (const float4*)(x + (size_t)warp * D);
    float4 v = xr[lane];
    float s  = v.x + v.y + v.z + v.w;
    float ss = v.x * v.x + v.y * v.y + v.z * v.z + v.w * v.w;
    #pragma unroll
    for (int o = 16; o; o >>= 1) {
        s  += __shfl_xor_sync(0xffffffffu, s,  o);
        ss += __shfl_xor_sync(0xffffffffu, ss, o);
    }
    float mu  = s * (1.0f / D);
    float var = ss * (1.0f / D) - mu * mu;
    float inv = rsqrtf(var + 1e-5f);
    float4 g = ((const float4*)gamma)[lane];
    float4 b = ((const float4*)beta)[lane];
    float4 m = ((const float4*)(mask + (size_t)warp * D))[lane];
    float2 p0, p1;
    p0.x = fmaxf((v.x - mu) * inv * g.x + b.x, 0.0f) * m.x;
    p0.y = fmaxf((v.y - mu) * inv * g.y + b.y, 0.0f) * m.y;
    p1.x = fmaxf((v.z - mu) * inv * g.z + b.z, 0.0f) * m.z;
    p1.y = fmaxf((v.w - mu) * inv * g.w + b.w, 0.0f) * m.w;
    __half2* dst = (__half2*)(g_A + (size_t)warp * 256 + 128 + lane * 4);
    dst[0] = __float22half2_rn(p0);
    dst[1] = __float22half2_rn(p1);
}

// ---------------- Stage B1: degree count (inline dtype detect) ----------------
__global__ void count_deg_kernel(const void* __restrict__ edges, int E,
                                 unsigned long long Nval) {
    int is32 = probe_is32(edges, Nval);
    if (blockIdx.x == 0 && threadIdx.x == 0) g_is32 = is32;
    long long gtid = blockIdx.x * (long long)blockDim.x + threadIdx.x;
    long long stride = (long long)gridDim.x * blockDim.x;
    if (is32) {
        const int* dst = (const int*)edges + E;
        const int4* d4 = (const int4*)dst;
        int n4 = E >> 2;
        for (long long i = gtid; i < n4; i += stride) {
            int4 v = d4[i];
            atomicAdd(&g_deg[v.x], 1);
            atomicAdd(&g_deg[v.y], 1);
            atomicAdd(&g_deg[v.z], 1);
            atomicAdd(&g_deg[v.w], 1);
        }
        int tail = E & 3;
        if (gtid < tail) atomicAdd(&g_deg[dst[(E & ~3) + (int)gtid]], 1);
    } else {
        const long long* dst = (const long long*)edges + E;
        const longlong2* d2 = (const longlong2*)dst;
        int n2 = E >> 1;
        for (long long i = gtid; i < n2; i += stride) {
            longlong2 v = d2[i];
            atomicAdd(&g_deg[(int)v.x], 1);
            atomicAdd(&g_deg[(int)v.y], 1);
        }
        if ((E & 1) && gtid == 0) atomicAdd(&g_deg[(int)dst[E - 1]], 1);
    }
}

// ---------------- Stage B2: single-pass decoupled-lookback scan ----------------
// Reads g_deg, writes g_start & g_cursor (exclusive prefix), clears g_deg.
__global__ void scan_kernel(int N) {
    __shared__ int ws[32];
    __shared__ int s_prefix;
    int b = blockIdx.x;
    int i = b * 1024 + threadIdx.x;
    int lane = threadIdx.x & 31, wid = threadIdx.x >> 5;

    int v = (i < N) ? g_deg[i] : 0;
    if (i < N) g_deg[i] = 0;        // reset for next replay
    int incl = v;
    #pragma unroll
    for (int o = 1; o < 32; o <<= 1) {
        int t = __shfl_up_sync(0xffffffffu, incl, o);
        if (lane >= o) incl += t;
    }
    if (lane == 31) ws[wid] = incl;
    __syncthreads();
    if (wid == 0) {
        int sv = ws[lane];
        int in2 = sv;
        #pragma unroll
        for (int o = 1; o < 32; o <<= 1) {
            int t = __shfl_up_sync(0xffffffffu, in2, o);
            if (lane >= o) in2 += t;
        }
        ws[lane] = in2 - sv;
    }
    __syncthreads();
    int excl = incl - v + ws[wid];
    int blockSum = __shfl_sync(0xffffffffu, excl + v, 31, 32); // need total: compute below
    // total of block = excl(last) + v(last); broadcast via shared
    __shared__ int s_total;
    if (threadIdx.x == 1023) s_total = excl + v;
    __syncthreads();
    blockSum = s_total;

    // publish aggregate (or prefix for block 0)
    if (threadIdx.x == 0) {
        unsigned long long pack = b == 0
            ? ((2ULL << 32) | (unsigned)blockSum)
            : ((1ULL << 32) | (unsigned)blockSum);
        atomicExch(&g_scanState[b], pack);
    }

    // lookback by warp 0
    if (wid == 0 && b > 0) {
        long long run = 0;
        int j = b - 1;
        while (true) {
            int idx = j - lane;
            unsigned long long s;
            unsigned status;
            do {
                s = (idx >= 0) ? atomicAdd(&g_scanState[idx], 0ULL)
                               : (1ULL << 32);
                status = (unsigned)(s >> 32);
            } while (__any_sync(0xffffffffu, status == 0));
            unsigned val = (unsigned)s;
            unsigned pmask = __ballot_sync(0xffffffffu, status == 2);
            if (pmask) {
                int fl = __ffs(pmask) - 1;          // nearest prefix lane
                long long c = (lane <= fl) ? (long long)val : 0;
                #pragma unroll
                for (int o = 16; o; o >>= 1) c += __shfl_xor_sync(0xffffffffu, c, o);
                run += c;
                break;
            } else {
                long long c = (idx >= 0) ? (long long)val : 0;
                #pragma unroll
                for (int o = 16; o; o >>= 1) c += __shfl_xor_sync(0xffffffffu, c, o);
                run += c;
                j -= 32;
            }
        }
        if (lane == 0) {
            atomicExch(&g_scanState[b], (2ULL << 32) | (unsigned)(run + blockSum));
            s_prefix = (int)run;
        }
    }
    if (b == 0 && threadIdx.x == 0) s_prefix = 0;
    __syncthreads();
    if (i < N) {
        int st = excl + s_prefix;
        g_start[i] = st;
        g_cursor[i] = st;
    }
}

// ---------------- Stage B3: scatter (inline detect; resets scan state) --------
__global__ void scatter_kernel(const void* __restrict__ edges, int E,
                               unsigned long long Nval) {
    int is32 = probe_is32(edges, Nval);
    if (blockIdx.x == 0 && threadIdx.x < 64) g_scanState[threadIdx.x] = 0ULL;
    long long gtid = blockIdx.x * (long long)blockDim.x + threadIdx.x;
    long long stride = (long long)gridDim.x * blockDim.x;
    if (is32) {
        const int4* s4 = (const int4*)edges;
        const int4* d4 = (const int4*)((const int*)edges + E);
        int n4 = E >> 2;
        for (long long i = gtid; i < n4; i += stride) {
            int4 sv = s4[i];
            int4 dv = d4[i];
            g_csr[atomicAdd(&g_cursor[dv.x], 1)] = sv.x;
            g_csr[atomicAdd(&g_cursor[dv.y], 1)] = sv.y;
            g_csr[atomicAdd(&g_cursor[dv.z], 1)] = sv.z;
            g_csr[atomicAdd(&g_cursor[dv.w], 1)] = sv.w;
        }
        int tail = E & 3;
        if (gtid < tail) {
            int e = (E & ~3) + (int)gtid;
            int src = ((const int*)edges)[e];
            int dst = ((const int*)edges)[E + e];
            g_csr[atomicAdd(&g_cursor[dst], 1)] = src;
        }
    } else {
        const longlong2* s2 = (const longlong2*)edges;
        const longlong2* d2 = (const longlong2*)((const long long*)edges + E);
        int n2 = E >> 1;
        for (long long i = gtid; i < n2; i += stride) {
            longlong2 sv = s2[i];
            longlong2 dv = d2[i];
            g_csr[atomicAdd(&g_cursor[(int)dv.x], 1)] = (int)sv.x;
            g_csr[atomicAdd(&g_cursor[(int)dv.y], 1)] = (int)sv.y;
        }
        if ((E & 1) && gtid == 0) {
            int src = (int)((const long long*)edges)[E - 1];
            int dst = (int)((const long long*)edges)[2 * E - 1];
            g_csr[atomicAdd(&g_cursor[dst], 1)] = src;
        }
    }
}

// ---------------- Stage B4: mean aggregation ----------------
__global__ void aggregate_kernel(int N, int E) {
    int warp = (blockIdx.x * blockDim.x + threadIdx.x) >> 5;
    int lane = threadIdx.x & 31;
    if (warp >= N) return;
    int st = g_start[warp];
    int en = (warp + 1 < N) ? g_start[warp + 1] : E;
    int d  = en - st;
    float2 acc0 = make_float2(0.f, 0.f);
    float2 acc1 = make_float2(0.f, 0.f);
    int j = st;
    for (; j + 4 <= en; j += 4) {
        int s0 = g_csr[j], s1 = g_csr[j + 1], s2 = g_csr[j + 2], s3 = g_csr[j + 3];
        const __half2* r0 = (const __half2*)(g_A + (size_t)s0 * 256 + 128 + lane * 4);
        const __half2* r1 = (const __half2*)(g_A + (size_t)s1 * 256 + 128 + lane * 4);
        const __half2* r2 = (const __half2*)(g_A + (size_t)s2 * 256 + 128 + lane * 4);
        const __half2* r3 = (const __half2*)(g_A + (size_t)s3 * 256 + 128 + lane * 4);
        float2 a, b;
        a = __half22float2(r0[0]); b = __half22float2(r0[1]);
        acc0.x += a.x; acc0.y += a.y; acc1.x += b.x; acc1.y += b.y;
        a = __half22float2(r1[0]); b = __half22float2(r1[1]);
        acc0.x += a.x; acc0.y += a.y; acc1.x += b.x; acc1.y += b.y;
        a = __half22float2(r2[0]); b = __half22float2(r2[1]);
        acc0.x += a.x; acc0.y += a.y; acc1.x += b.x; acc1.y += b.y;
        a = __half22float2(r3[0]); b = __half22float2(r3[1]);
        acc0.x += a.x; acc0.y += a.y; acc1.x += b.x; acc1.y += b.y;
    }
    for (; j < en; ++j) {
        int s0 = g_csr[j];
        const __half2* r0 = (const __half2*)(g_A + (size_t)s0 * 256 + 128 + lane * 4);
        float2 a = __half22float2(r0[0]);
        float2 b = __half22float2(r0[1]);
        acc0.x += a.x; acc0.y += a.y; acc1.x += b.x; acc1.y += b.y;
    }
    float invd = 1.0f / fmaxf((float)d, 1.0f);
    acc0.x *= invd; acc0.y *= invd; acc1.x *= invd; acc1.y *= invd;
    __half2* dst = (__half2*)(g_A + (size_t)warp * 256 + lane * 4);
    dst[0] = __float22half2_rn(acc0);
    dst[1] = __float22half2_rn(acc1);
}

// ---------------- Stage C0: fused fp16 weights ----------------
__global__ void build_w_kernel(const float* __restrict__ wl,
                               const float* __restrict__ wr) {
    int idx = blockIdx.x * blockDim.x + threadIdx.x;
    if (idx >= 128 * 256) return;
    int n = idx >> 8;
    int k = idx & 255;
    float v = (k < 128) ? wl[n * 128 + k] : wr[n * 128 + (k - 128)];
    g_W[idx] = __float2half_rn(v);
}

// ---------------- Stage C: fp16 mma GEMM with cp.async double buffer --------
#define B_OFF  0
#define A0_OFF 65536
#define ABUF_SZ 16384
#define GSMEM_TOTAL (65536 + 2 * ABUF_SZ)

__global__ __launch_bounds__(256) void mma_gemm_kernel(const float* __restrict__ bias,
                                                       float* __restrict__ out, int N) {
    extern __shared__ char smem[];
    uint32_t sb = smem_u32(smem);
    int tid = threadIdx.x;
    int lane = tid & 31;
    int wid = tid >> 5;
    int warp_m = wid & 3;
    int warp_n = wid >> 2;
    int rowBase = blockIdx.x * 128;

    // issue B (cp.async) — group 0 together with A chunk 0
    for (int idx = tid; idx < 4096; idx += 256) {
        int r  = idx >> 5;
        int ck = idx & 31;
        uint32_t off = (uint32_t)r * 512 + ((uint32_t)(ck ^ (r & 7)) << 4);
        CP_ASYNC16(sb + B_OFF + off, (const char*)(g_W + (size_t)r * 256 + ck * 8));
    }
    // A chunk stage helper (c = chunk 0..3, buf = 0/1)
    #define STAGE_A(c, buf)                                                        \
        for (int idx = tid; idx < 1024; idx += 256) {                              \
            int r  = idx >> 3;                                                     \
            int ck = idx & 7;                                                      \
            CP_ASYNC16(sb + A0_OFF + (buf) * ABUF_SZ + r * 128                     \
                           + ((uint32_t)(ck ^ (r & 7)) << 4),                      \
                       (const char*)(g_A + (size_t)(rowBase + r) * 256             \
                                     + (c) * 64 + ck * 8));                        \
        }
    STAGE_A(0, 0);
    CP_COMMIT();

    float acc[2][8][4];
    #pragma unroll
    for (int i = 0; i < 2; i++)
        #pragma unroll
        for (int j = 0; j < 8; j++)
            #pragma unroll
            for (int q = 0; q < 4; q++) acc[i][j][q] = 0.0f;

    int aRow = (lane & 7) + ((lane >> 3) & 1) * 8;
    int aK8  = (lane >> 4) * 8;
    int bN   = (lane & 7) + (lane >> 4) * 8;
    int bK8  = ((lane >> 3) & 1) * 8;

    #pragma unroll
    for (int c = 0; c < 4; ++c) {
        if (c < 3) {
            STAGE_A(c + 1, (c + 1) & 1);
            CP_COMMIT();
            CP_WAIT(1);
        } else {
            CP_WAIT(0);
        }
        __syncthreads();
        uint32_t abase = sb + A0_OFF + (c & 1) * ABUF_SZ;
        #pragma unroll
        for (int ks = 0; ks < 4; ++ks) {
            int kk = ks * 16;
            uint32_t a[2][4];
            #pragma unroll
            for (int mf = 0; mf < 2; ++mf) {
                int row = warp_m * 32 + mf * 16 + aRow;
                int kA  = kk + aK8;
                uint32_t addr = abase + (uint32_t)row * 128
                              + ((uint32_t)(((kA >> 3) ^ (row & 7))) << 4);
                ldmat_x4(addr, a[mf]);
            }
            int gk = c * 64 + kk;
            #pragma unroll
            for (int j = 0; j < 4; ++j) {
                int n  = warp_n * 64 + j * 16 + bN;
                int kB = gk + bK8;
                uint32_t addr = sb + B_OFF + (uint32_t)n * 512
                              + ((uint32_t)(((kB >> 3) ^ (n & 7))) << 4);
                uint32_t b[4];
                ldmat_x4(addr, b);
                mma16816(acc[0][2 * j],     a[0], b[0], b[1]);
                mma16816(acc[0][2 * j + 1], a[0], b[2], b[3]);
                mma16816(acc[1][2 * j],     a[1], b[0], b[1]);
                mma16816(acc[1][2 * j + 1], a[1], b[2], b[3]);
            }
        }
        __syncthreads();
    }

    float2 bcol[8];
    #pragma unroll
    for (int nf = 0; nf < 8; ++nf) {
        int col = warp_n * 64 + nf * 8 + (lane & 3) * 2;
        bcol[nf] = *(const float2*)(bias + col);
    }
    #pragma unroll
    for (int mf = 0; mf < 2; ++mf) {
        int r0 = rowBase + warp_m * 32 + mf * 16 + (lane >> 2);
        #pragma unroll
        for (int h = 0; h < 2; ++h) {
            int row = r0 + h * 8;
            if (row < N) {
                #pragma unroll
                for (int nf = 0; nf < 8; ++nf) {
                    int col = warp_n * 64 + nf * 8 + (lane & 3) * 2;
                    float2 o;
                    o.x = acc[mf][nf][h * 2 + 0] + bcol[nf].x;
                    o.y = acc[mf][nf][h * 2 + 1] + bcol[nf].y;
                    *(float2*)(out + (size_t)row * D + col) = o;
                }
            }
        }
    }
}

// ---------------- launch ----------------
extern "C" void kernel_launch(void* const* d_in, const int* in_sizes, int n_in,
                              void* d_out, int out_size) {
    const float* x     = (const float*)d_in[0];
    const void*  edges =               d_in[1];
    const float* mask  = (const float*)d_in[2];
    const float* gamma = (const float*)d_in[3];
    const float* beta  = (const float*)d_in[4];
    const float* wl    = (const float*)d_in[5];
    const float* bl    = (const float*)d_in[6];
    const float* wr    = (const float*)d_in[7];
    float* out = (float*)d_out;

    int N = in_sizes[0] / D;
    int E = in_sizes[1] / 2;

    static cudaStream_t s2 = nullptr;
    static cudaEvent_t evRoot = nullptr, evB = nullptr;
    if (!s2) {
        cudaStreamCreateWithFlags(&s2, cudaStreamNonBlocking);
        cudaEventCreateWithFlags(&evRoot, cudaEventDisableTiming);
        cudaEventCreateWithFlags(&evB, cudaEventDisableTiming);
        cudaFuncSetAttribute(mma_gemm_kernel,
                             cudaFuncAttributeMaxDynamicSharedMemorySize, GSMEM_TOTAL);
    }

    int nb = (N + 1023) / 1024;

    // fork: CSR chain on s2 (3 kernels)
    cudaEventRecord(evRoot, 0);
    cudaStreamWaitEvent(s2, evRoot, 0);
    count_deg_kernel<<<512, 256, 0, s2>>>(edges, E, (unsigned long long)N);
    scan_kernel<<<nb, 1024, 0, s2>>>(N);
    scatter_kernel<<<512, 256, 0, s2>>>(edges, E, (unsigned long long)N);
    cudaEventRecord(evB, s2);

    // main stream: LN + weight prep (concurrent)
    ln_relu_mask_kernel<<<(N + 7) / 8, 256>>>(x, mask, gamma, beta, N);
    build_w_kernel<<<(128 * 256 + 255) / 256, 256>>>(wl, wr);

    // join, then aggregate + GEMM
    cudaStreamWaitEvent(0, evB, 0);
    aggregate_kernel<<<(N + 7) / 8, 256>>>(N, E);
    mma_gemm_kernel<<<(N + 127) / 128, 256, GSMEM_TOTAL>>>(bl, out, N);
}

// round 7
// speedup vs baseline: 2.2437x; 1.0209x over previous
#include <cuda_runtime.h>
#include <cuda_bf16.h>
#include <cuda_fp16.h>
#include <cstdint>

// ---------------- problem-size constants ----------------
#define MAX_N 50176
#define MAX_E 800000
#define D 128

// ---------------- device scratch ----------------
__device__ __half g_A[(size_t)MAX_N * 256];   // cols [0,128)=agg, [128,256)=h
__device__ __half g_W[128 * 256];             // fused weights [n][k] fp16
__device__ int   g_deg[MAX_N];                // zero at kernel-entry invariant
__device__ int   g_start[MAX_N];
__device__ int   g_cursor[MAX_N];
__device__ int   g_csr[MAX_E];
__device__ unsigned long long g_scanState[64]; // lookback: (status<<32)|value

// ---------------- helpers ----------------
__device__ __forceinline__ uint32_t smem_u32(const void* p) {
    uint32_t a;
    asm("{ .reg .u64 t; cvta.to.shared.u64 t, %1; cvt.u32.u64 %0, t; }" : "=r"(a) : "l"(p));
    return a;
}

__device__ __forceinline__ void ldmat_x4(uint32_t addr, uint32_t* r) {
    asm volatile("ldmatrix.sync.aligned.m8n8.x4.shared.b16 {%0,%1,%2,%3}, [%4];"
                 : "=r"(r[0]), "=r"(r[1]), "=r"(r[2]), "=r"(r[3]) : "r"(addr));
}

__device__ __forceinline__ void mma16816(float* d, const uint32_t* a,
                                         uint32_t b0, uint32_t b1) {
    asm volatile(
        "mma.sync.aligned.m16n8k16.row.col.f32.f16.f16.f32 "
        "{%0,%1,%2,%3}, {%4,%5,%6,%7}, {%8,%9}, {%0,%1,%2,%3};"
        : "+f"(d[0]), "+f"(d[1]), "+f"(d[2]), "+f"(d[3])
        : "r"(a[0]), "r"(a[1]), "r"(a[2]), "r"(a[3]), "r"(b0), "r"(b1));
}

#define CP_ASYNC16(dst, src) \
    asm volatile("cp.async.cg.shared.global [%0], [%1], 16;" :: "r"(dst), "l"(src))
#define CP_COMMIT() asm volatile("cp.async.commit_group;")
#define CP_WAIT(n)  asm volatile("cp.async.wait_group %0;" :: "n"(n))

// inline dtype probe: true if buffer is int32 (any of first 64 u64 words >= N)
__device__ __forceinline__ int probe_is32(const void* edges, unsigned long long Nval) {
    const unsigned long long* e = (const unsigned long long*)edges;
    int bad = 0;
    if (threadIdx.x < 64) bad = (e[threadIdx.x] >= Nval);
    return __syncthreads_or(bad);
}

// ---------------- Stage A: LN + ReLU + dropout -> fp16 (2 rows/warp) --------
__global__ void ln_relu_mask_kernel(const float* __restrict__ x,
                                    const float* __restrict__ mask,
                                    const float* __restrict__ gamma,
                                    const float* __restrict__ beta,
                                    int N) {
    int warp = (blockIdx.x * blockDim.x + threadIdx.x) >> 5;
    int lane = threadIdx.x & 31;
    int row0 = warp * 2;
    if (row0 >= N) return;
    bool has1 = (row0 + 1) < N;
    const float4* xr0 = (const float4*)(x + (size_t)row0 * D);
    const float4* xr1 = (const float4*)(x + (size_t)(row0 + 1) * D);
    const float4* mr0 = (const float4*)(mask + (size_t)row0 * D);
    const float4* mr1 = (const float4*)(mask + (size_t)(row0 + 1) * D);
    float4 v0 = xr0[lane];
    float4 v1 = has1 ? xr1[lane] : make_float4(0.f, 0.f, 0.f, 0.f);
    float4 m0 = mr0[lane];
    float4 m1 = has1 ? mr1[lane] : make_float4(0.f, 0.f, 0.f, 0.f);
    float4 g = ((const float4*)gamma)[lane];
    float4 b = ((const float4*)beta)[lane];

    float s0 = v0.x + v0.y + v0.z + v0.w;
    float q0 = v0.x * v0.x + v0.y * v0.y + v0.z * v0.z + v0.w * v0.w;
    float s1 = v1.x + v1.y + v1.z + v1.w;
    float q1 = v1.x * v1.x + v1.y * v1.y + v1.z * v1.z + v1.w * v1.w;
    #pragma unroll
    for (int o = 16; o; o >>= 1) {
        s0 += __shfl_xor_sync(0xffffffffu, s0, o);
        q0 += __shfl_xor_sync(0xffffffffu, q0, o);
        s1 += __shfl_xor_sync(0xffffffffu, s1, o);
        q1 += __shfl_xor_sync(0xffffffffu, q1, o);
    }
    float mu0  = s0 * (1.0f / D);
    float inv0 = rsqrtf(q0 * (1.0f / D) - mu0 * mu0 + 1e-5f);
    float mu1  = s1 * (1.0f / D);
    float inv1 = rsqrtf(q1 * (1.0f / D) - mu1 * mu1 + 1e-5f);

    float2 p0, p1;
    p0.x = fmaxf((v0.x - mu0) * inv0 * g.x + b.x, 0.0f) * m0.x;
    p0.y = fmaxf((v0.y - mu0) * inv0 * g.y + b.y, 0.0f) * m0.y;
    p1.x = fmaxf((v0.z - mu0) * inv0 * g.z + b.z, 0.0f) * m0.z;
    p1.y = fmaxf((v0.w - mu0) * inv0 * g.w + b.w, 0.0f) * m0.w;
    __half2* dst0 = (__half2*)(g_A + (size_t)row0 * 256 + 128 + lane * 4);
    dst0[0] = __float22half2_rn(p0);
    dst0[1] = __float22half2_rn(p1);
    if (has1) {
        p0.x = fmaxf((v1.x - mu1) * inv1 * g.x + b.x, 0.0f) * m1.x;
        p0.y = fmaxf((v1.y - mu1) * inv1 * g.y + b.y, 0.0f) * m1.y;
        p1.x = fmaxf((v1.z - mu1) * inv1 * g.z + b.z, 0.0f) * m1.z;
        p1.y = fmaxf((v1.w - mu1) * inv1 * g.w + b.w, 0.0f) * m1.w;
        __half2* dst1 = (__half2*)(g_A + (size_t)(row0 + 1) * 256 + 128 + lane * 4);
        dst1[0] = __float22half2_rn(p0);
        dst1[1] = __float22half2_rn(p1);
    }
}

// ---------------- Stage B1: degree count (one vector per thread) -------------
__global__ void count_deg_kernel(const void* __restrict__ edges, int E,
                                 unsigned long long Nval) {
    int is32 = probe_is32(edges, Nval);
    long long gtid = blockIdx.x * (long long)blockDim.x + threadIdx.x;
    if (is32) {
        const int* dst = (const int*)edges + E;
        int n4 = E >> 2;
        if (gtid < n4) {
            int4 v = ((const int4*)dst)[gtid];
            atomicAdd(&g_deg[v.x], 1);
            atomicAdd(&g_deg[v.y], 1);
            atomicAdd(&g_deg[v.z], 1);
            atomicAdd(&g_deg[v.w], 1);
        }
        int tail = E & 3;
        if (gtid >= n4 && gtid < n4 + tail)
            atomicAdd(&g_deg[dst[(E & ~3) + (int)(gtid - n4)]], 1);
    } else {
        const long long* dst = (const long long*)edges + E;
        int n2 = E >> 1;
        if (gtid < n2) {
            longlong2 v = ((const longlong2*)dst)[gtid];
            atomicAdd(&g_deg[(int)v.x], 1);
            atomicAdd(&g_deg[(int)v.y], 1);
        }
        if ((E & 1) && gtid == n2) atomicAdd(&g_deg[(int)dst[E - 1]], 1);
    }
}

// ---------------- Stage B2: single-pass decoupled-lookback scan ----------------
__global__ void scan_kernel(int N) {
    __shared__ int ws[32];
    __shared__ int s_prefix;
    __shared__ int s_total;
    int b = blockIdx.x;
    int i = b * 1024 + threadIdx.x;
    int lane = threadIdx.x & 31, wid = threadIdx.x >> 5;

    int v = (i < N) ? g_deg[i] : 0;
    if (i < N) g_deg[i] = 0;        // reset for next replay
    int incl = v;
    #pragma unroll
    for (int o = 1; o < 32; o <<= 1) {
        int t = __shfl_up_sync(0xffffffffu, incl, o);
        if (lane >= o) incl += t;
    }
    if (lane == 31) ws[wid] = incl;
    __syncthreads();
    if (wid == 0) {
        int sv = ws[lane];
        int in2 = sv;
        #pragma unroll
        for (int o = 1; o < 32; o <<= 1) {
            int t = __shfl_up_sync(0xffffffffu, in2, o);
            if (lane >= o) in2 += t;
        }
        ws[lane] = in2 - sv;
    }
    __syncthreads();
    int excl = incl - v + ws[wid];
    if (threadIdx.x == 1023) s_total = excl + v;
    __syncthreads();
    int blockSum = s_total;

    if (threadIdx.x == 0) {
        unsigned long long pack = b == 0
            ? ((2ULL << 32) | (unsigned)blockSum)
            : ((1ULL << 32) | (unsigned)blockSum);
        atomicExch(&g_scanState[b], pack);
    }

    if (wid == 0 && b > 0) {
        long long run = 0;
        int j = b - 1;
        while (true) {
            int idx = j - lane;
            unsigned long long s;
            unsigned status;
            do {
                s = (idx >= 0) ? atomicAdd(&g_scanState[idx], 0ULL)
                               : (1ULL << 32);
                status = (unsigned)(s >> 32);
            } while (__any_sync(0xffffffffu, status == 0));
            unsigned val = (unsigned)s;
            unsigned pmask = __ballot_sync(0xffffffffu, status == 2);
            if (pmask) {
                int fl = __ffs(pmask) - 1;
                long long c = (lane <= fl) ? (long long)val : 0;
                #pragma unroll
                for (int o = 16; o; o >>= 1) c += __shfl_xor_sync(0xffffffffu, c, o);
                run += c;
                break;
            } else {
                long long c = (idx >= 0) ? (long long)val : 0;
                #pragma unroll
                for (int o = 16; o; o >>= 1) c += __shfl_xor_sync(0xffffffffu, c, o);
                run += c;
                j -= 32;
            }
        }
        if (lane == 0) {
            atomicExch(&g_scanState[b], (2ULL << 32) | (unsigned)(run + blockSum));
            s_prefix = (int)run;
        }
    }
    if (b == 0 && threadIdx.x == 0) s_prefix = 0;
    __syncthreads();
    if (i < N) {
        int st = excl + s_prefix;
        g_start[i] = st;
        g_cursor[i] = st;
    }
}

// ---------------- Stage B3: scatter (one vector per thread) ----------------
__global__ void scatter_kernel(const void* __restrict__ edges, int E,
                               unsigned long long Nval) {
    int is32 = probe_is32(edges, Nval);
    if (blockIdx.x == 0 && threadIdx.x < 64) g_scanState[threadIdx.x] = 0ULL;
    long long gtid = blockIdx.x * (long long)blockDim.x + threadIdx.x;
    if (is32) {
        int n4 = E >> 2;
        if (gtid < n4) {
            int4 sv = ((const int4*)edges)[gtid];
            int4 dv = ((const int4*)((const int*)edges + E))[gtid];
            g_csr[atomicAdd(&g_cursor[dv.x], 1)] = sv.x;
            g_csr[atomicAdd(&g_cursor[dv.y], 1)] = sv.y;
            g_csr[atomicAdd(&g_cursor[dv.z], 1)] = sv.z;
            g_csr[atomicAdd(&g_cursor[dv.w], 1)] = sv.w;
        }
        int tail = E & 3;
        if (gtid >= n4 && gtid < n4 + tail) {
            int e = (E & ~3) + (int)(gtid - n4);
            int src = ((const int*)edges)[e];
            int dst = ((const int*)edges)[E + e];
            g_csr[atomicAdd(&g_cursor[dst], 1)] = src;
        }
    } else {
        int n2 = E >> 1;
        if (gtid < n2) {
            longlong2 sv = ((const longlong2*)edges)[gtid];
            longlong2 dv = ((const longlong2*)((const long long*)edges + E))[gtid];
            g_csr[atomicAdd(&g_cursor[(int)dv.x], 1)] = (int)sv.x;
            g_csr[atomicAdd(&g_cursor[(int)dv.y], 1)] = (int)sv.y;
        }
        if ((E & 1) && gtid == n2) {
            int src = (int)((const long long*)edges)[E - 1];
            int dst = (int)((const long long*)edges)[2 * E - 1];
            g_csr[atomicAdd(&g_cursor[dst], 1)] = src;
        }
    }
}

// ---------------- Stage B4: mean aggregation ----------------
__global__ void aggregate_kernel(int N, int E) {
    int warp = (blockIdx.x * blockDim.x + threadIdx.x) >> 5;
    int lane = threadIdx.x & 31;
    if (warp >= N) return;
    int st = g_start[warp];
    int en = (warp + 1 < N) ? g_start[warp + 1] : E;
    int d  = en - st;
    float2 acc0 = make_float2(0.f, 0.f);
    float2 acc1 = make_float2(0.f, 0.f);
    int j = st;
    for (; j + 4 <= en; j += 4) {
        int s0 = g_csr[j], s1 = g_csr[j + 1], s2 = g_csr[j + 2], s3 = g_csr[j + 3];
        const __half2* r0 = (const __half2*)(g_A + (size_t)s0 * 256 + 128 + lane * 4);
        const __half2* r1 = (const __half2*)(g_A + (size_t)s1 * 256 + 128 + lane * 4);
        const __half2* r2 = (const __half2*)(g_A + (size_t)s2 * 256 + 128 + lane * 4);
        const __half2* r3 = (const __half2*)(g_A + (size_t)s3 * 256 + 128 + lane * 4);
        float2 a, b;
        a = __half22float2(r0[0]); b = __half22float2(r0[1]);
        acc0.x += a.x; acc0.y += a.y; acc1.x += b.x; acc1.y += b.y;
        a = __half22float2(r1[0]); b = __half22float2(r1[1]);
        acc0.x += a.x; acc0.y += a.y; acc1.x += b.x; acc1.y += b.y;
        a = __half22float2(r2[0]); b = __half22float2(r2[1]);
        acc0.x += a.x; acc0.y += a.y; acc1.x += b.x; acc1.y += b.y;
        a = __half22float2(r3[0]); b = __half22float2(r3[1]);
        acc0.x += a.x; acc0.y += a.y; acc1.x += b.x; acc1.y += b.y;
    }
    for (; j < en; ++j) {
        int s0 = g_csr[j];
        const __half2* r0 = (const __half2*)(g_A + (size_t)s0 * 256 + 128 + lane * 4);
        float2 a = __half22float2(r0[0]);
        float2 b = __half22float2(r0[1]);
        acc0.x += a.x; acc0.y += a.y; acc1.x += b.x; acc1.y += b.y;
    }
    float invd = 1.0f / fmaxf((float)d, 1.0f);
    acc0.x *= invd; acc0.y *= invd; acc1.x *= invd; acc1.y *= invd;
    __half2* dst = (__half2*)(g_A + (size_t)warp * 256 + lane * 4);
    dst[0] = __float22half2_rn(acc0);
    dst[1] = __float22half2_rn(acc1);
}

// ---------------- Stage C0: fused fp16 weights ----------------
__global__ void build_w_kernel(const float* __restrict__ wl,
                               const float* __restrict__ wr) {
    int idx = blockIdx.x * blockDim.x + threadIdx.x;
    if (idx >= 128 * 256) return;
    int n = idx >> 8;
    int k = idx & 255;
    float v = (k < 128) ? wl[n * 128 + k] : wr[n * 128 + (k - 128)];
    g_W[idx] = __float2half_rn(v);
}

// ---------------- Stage C: fp16 mma GEMM with cp.async double buffer --------
#define B_OFF  0
#define A0_OFF 65536
#define ABUF_SZ 16384
#define GSMEM_TOTAL (65536 + 2 * ABUF_SZ)

__global__ __launch_bounds__(256) void mma_gemm_kernel(const float* __restrict__ bias,
                                                       float* __restrict__ out, int N) {
    extern __shared__ char smem[];
    uint32_t sb = smem_u32(smem);
    int tid = threadIdx.x;
    int lane = tid & 31;
    int wid = tid >> 5;
    int warp_m = wid & 3;
    int warp_n = wid >> 2;
    int rowBase = blockIdx.x * 128;

    for (int idx = tid; idx < 4096; idx += 256) {
        int r  = idx >> 5;
        int ck = idx & 31;
        uint32_t off = (uint32_t)r * 512 + ((uint32_t)(ck ^ (r & 7)) << 4);
        CP_ASYNC16(sb + B_OFF + off, (const char*)(g_W + (size_t)r * 256 + ck * 8));
    }
    #define STAGE_A(c, buf)                                                        \
        for (int idx = tid; idx < 1024; idx += 256) {                              \
            int r  = idx >> 3;                                                     \
            int ck = idx & 7;                                                      \
            CP_ASYNC16(sb + A0_OFF + (buf) * ABUF_SZ + r * 128                     \
                           + ((uint32_t)(ck ^ (r & 7)) << 4),                      \
                       (const char*)(g_A + (size_t)(rowBase + r) * 256             \
                                     + (c) * 64 + ck * 8));                        \
        }
    STAGE_A(0, 0);
    CP_COMMIT();

    float acc[2][8][4];
    #pragma unroll
    for (int i = 0; i < 2; i++)
        #pragma unroll
        for (int j = 0; j < 8; j++)
            #pragma unroll
            for (int q = 0; q < 4; q++) acc[i][j][q] = 0.0f;

    int aRow = (lane & 7) + ((lane >> 3) & 1) * 8;
    int aK8  = (lane >> 4) * 8;
    int bN   = (lane & 7) + (lane >> 4) * 8;
    int bK8  = ((lane >> 3) & 1) * 8;

    #pragma unroll
    for (int c = 0; c < 4; ++c) {
        if (c < 3) {
            STAGE_A(c + 1, (c + 1) & 1);
            CP_COMMIT();
            CP_WAIT(1);
        } else {
            CP_WAIT(0);
        }
        __syncthreads();
        uint32_t abase = sb + A0_OFF + (c & 1) * ABUF_SZ;
        #pragma unroll
        for (int ks = 0; ks < 4; ++ks) {
            int kk = ks * 16;
            uint32_t a[2][4];
            #pragma unroll
            for (int mf = 0; mf < 2; ++mf) {
                int row = warp_m * 32 + mf * 16 + aRow;
                int kA  = kk + aK8;
                uint32_t addr = abase + (uint32_t)row * 128
                              + ((uint32_t)(((kA >> 3) ^ (row & 7))) << 4);
                ldmat_x4(addr, a[mf]);
            }
            int gk = c * 64 + kk;
            #pragma unroll
            for (int j = 0; j < 4; ++j) {
                int n  = warp_n * 64 + j * 16 + bN;
                int kB = gk + bK8;
                uint32_t addr = sb + B_OFF + (uint32_t)n * 512
                              + ((uint32_t)(((kB >> 3) ^ (n & 7))) << 4);
                uint32_t b[4];
                ldmat_x4(addr, b);
                mma16816(acc[0][2 * j],     a[0], b[0], b[1]);
                mma16816(acc[0][2 * j + 1], a[0], b[2], b[3]);
                mma16816(acc[1][2 * j],     a[1], b[0], b[1]);
                mma16816(acc[1][2 * j + 1], a[1], b[2], b[3]);
            }
        }
        __syncthreads();
    }

    float2 bcol[8];
    #pragma unroll
    for (int nf = 0; nf < 8; ++nf) {
        int col = warp_n * 64 + nf * 8 + (lane & 3) * 2;
        bcol[nf] = *(const float2*)(bias + col);
    }
    #pragma unroll
    for (int mf = 0; mf < 2; ++mf) {
        int r0 = rowBase + warp_m * 32 + mf * 16 + (lane >> 2);
        #pragma unroll
        for (int h = 0; h < 2; ++h) {
            int row = r0 + h * 8;
            if (row < N) {
                #pragma unroll
                for (int nf = 0; nf < 8; ++nf) {
                    int col = warp_n * 64 + nf * 8 + (lane & 3) * 2;
                    float2 o;
                    o.x = acc[mf][nf][h * 2 + 0] + bcol[nf].x;
                    o.y = acc[mf][nf][h * 2 + 1] + bcol[nf].y;
                    *(float2*)(out + (size_t)row * D + col) = o;
                }
            }
        }
    }
}

// ---------------- launch ----------------
extern "C" void kernel_launch(void* const* d_in, const int* in_sizes, int n_in,
                              void* d_out, int out_size) {
    const float* x     = (const float*)d_in[0];
    const void*  edges =               d_in[1];
    const float* mask  = (const float*)d_in[2];
    const float* gamma = (const float*)d_in[3];
    const float* beta  = (const float*)d_in[4];
    const float* wl    = (const float*)d_in[5];
    const float* bl    = (const float*)d_in[6];
    const float* wr    = (const float*)d_in[7];
    float* out = (float*)d_out;

    int N = in_sizes[0] / D;
    int E = in_sizes[1] / 2;

    static cudaStream_t s2 = nullptr;
    static cudaEvent_t evRoot = nullptr, evB = nullptr;
    if (!s2) {
        cudaStreamCreateWithFlags(&s2, cudaStreamNonBlocking);
        cudaEventCreateWithFlags(&evRoot, cudaEventDisableTiming);
        cudaEventCreateWithFlags(&evB, cudaEventDisableTiming);
        cudaFuncSetAttribute(mma_gemm_kernel,
                             cudaFuncAttributeMaxDynamicSharedMemorySize, GSMEM_TOTAL);
    }

    int nb = (N + 1023) / 1024;
    // one vector element per thread (int64 case needs E/2 threads + tail)
    int ethreads = E / 2 + 2;
    int eblocks = (ethreads + 255) / 256;

    // fork: CSR chain on s2 (3 kernels)
    cudaEventRecord(evRoot, 0);
    cudaStreamWaitEvent(s2, evRoot, 0);
    count_deg_kernel<<<eblocks, 256, 0, s2>>>(edges, E, (unsigned long long)N);
    scan_kernel<<<nb, 1024, 0, s2>>>(N);
    scatter_kernel<<<eblocks, 256, 0, s2>>>(edges, E, (unsigned long long)N);
    cudaEventRecord(evB, s2);

    // main stream: LN + weight prep (concurrent)
    ln_relu_mask_kernel<<<(N / 2 + 7) / 8, 256>>>(x, mask, gamma, beta, N);
    build_w_kernel<<<(128 * 256 + 255) / 256, 256>>>(wl, wr);

    // join, then aggregate + GEMM
    cudaStreamWaitEvent(0, evB, 0);
    aggregate_kernel<<<(N + 7) / 8, 256>>>(N, E);
    mma_gemm_kernel<<<(N + 127) / 128, 256, GSMEM_TOTAL>>>(bl, out, N);
}